// round 4
// baseline (speedup 1.0000x reference)
#include <cuda_runtime.h>

#define C_IN   512
#define IH     38
#define IW     50
#define HWPIX  1900
#define NANCH  17100
#define NSEL   8192
#define PRE_N  6000
#define POST_N 300
#define MASKW  94        // ceil(6000/64)
#define NBUCK  32768

typedef unsigned long long ull;

// ---------------- device scratch (static, no allocation) ----------------
__device__ float    g_h1T[HWPIX * 512];                // conv output, [pixel][k]
__device__ float    g_box[NANCH * 4];                  // decoded clipped boxes
__device__ ull      g_keys[NANCH];                     // (score<<32)|~idx
__device__ ull      g_sel[NSEL];                       // candidate keys + pad
__device__ unsigned g_hist[NBUCK];                     // 15-bit bucket histogram
__device__ float    g_tb[PRE_N * 4];                   // top-6000 boxes (sorted)
__device__ ull      g_mask[(size_t)PRE_N * MASKW];     // lower tri never written
__device__ ull      g_validw[128];                     // validity bits of top-6000

__constant__ float c_ab[9][4] = {
  {-37.254833f,  -82.50967f,   53.254833f,  98.50967f},
  {-82.50967f,  -173.01933f,   98.50967f,  189.01933f},
  {-173.01933f, -354.03867f,  189.01933f,  370.03867f},
  {-56.0f,       -56.0f,        72.0f,       72.0f},
  {-120.0f,     -120.0f,       136.0f,      136.0f},
  {-248.0f,     -248.0f,       264.0f,      264.0f},
  {-82.50967f,   -37.254833f,  98.50967f,   53.254833f},
  {-173.01933f,  -82.50967f,  189.01933f,   98.50967f},
  {-354.03867f, -173.01933f,  370.03867f,  189.01933f}};

// ---------------- f32x2 helpers ----------------
__device__ __forceinline__ ull dup2(float v) {
  ull r; asm("mov.b64 %0, {%1, %1};" : "=l"(r) : "f"(v)); return r;
}
__device__ __forceinline__ void fma2(ull& d, ull a, ull b) {
  asm("fma.rn.f32x2 %0, %1, %2, %0;" : "+l"(d) : "l"(a), "l"(b));
}
__device__ __forceinline__ float2 unpk(ull v) {
  float2 f; asm("mov.b64 {%0, %1}, %2;" : "=f"(f.x), "=f"(f.y) : "l"(v)); return f;
}

// ---------------- 3x3 conv + bias + relu -> g_h1T[p][k] ----------------
__global__ __launch_bounds__(256) void conv3x3_relu(
    const float* __restrict__ x, const float* __restrict__ wgt,
    const float* __restrict__ bias) {
  const int wt = blockIdx.x;            // 0..6
  const int ht = blockIdx.y;            // 0..4
  const int kt = blockIdx.z;            // 0..7
  const int h0 = ht * 8, w0 = wt * 8;
  const int tid = threadIdx.x;
  const int ty  = tid >> 4;             // 0..15 (k groups of 4)
  const int txp = tid & 15;
  const int hh  = txp >> 1;             // 0..7
  const int wq  = txp & 1;              // 0..1 (w groups of 4)

  __shared__ float sW[72 * 66];                     // [crs][k], stride 66
  __shared__ __align__(16) float sX[8][10][12];     // [c][row][col]

  ull a00 = 0, a01 = 0, a02 = 0, a03 = 0;
  ull a10 = 0, a11 = 0, a12 = 0, a13 = 0;

  const int k0g = kt * 64;

  for (int c0 = 0; c0 < C_IN; c0 += 8) {
    __syncthreads();
#pragma unroll
    for (int l = 0; l < 18; ++l) {
      int idx = tid + l * 256;          // = k*72 + crs
      int k = idx / 72, crs = idx % 72;
      sW[crs * 66 + k] = wgt[(size_t)(k0g + k) * 4608 + (size_t)c0 * 9 + crs];
    }
    for (int idx = tid; idx < 800; idx += 256) {
      int c = idx / 100, rem = idx % 100;
      int row = rem / 10, col = rem % 10;
      int gh = h0 - 1 + row, gw = w0 - 1 + col;
      float v = 0.f;
      if (gh >= 0 && gh < IH && gw >= 0 && gw < IW)
        v = x[(size_t)(c0 + c) * HWPIX + gh * IW + gw];
      sX[c][row][col] = v;
    }
    __syncthreads();

#pragma unroll 2
    for (int c = 0; c < 8; ++c) {
#pragma unroll
      for (int r = 0; r < 3; ++r) {
        const float* xp = &sX[c][hh + r][wq * 4];
        float4 xa = *(const float4*)xp;
        float2 xb = *(const float2*)(xp + 4);
        ull xd[6] = {dup2(xa.x), dup2(xa.y), dup2(xa.z),
                     dup2(xa.w), dup2(xb.x), dup2(xb.y)};
#pragma unroll
        for (int s = 0; s < 3; ++s) {
          int wi = (c * 9 + r * 3 + s) * 66 + ty * 4;
          ull w01 = *(const ull*)&sW[wi];
          ull w23 = *(const ull*)&sW[wi + 2];
          fma2(a00, w01, xd[s + 0]);
          fma2(a01, w01, xd[s + 1]);
          fma2(a02, w01, xd[s + 2]);
          fma2(a03, w01, xd[s + 3]);
          fma2(a10, w23, xd[s + 0]);
          fma2(a11, w23, xd[s + 1]);
          fma2(a12, w23, xd[s + 2]);
          fma2(a13, w23, xd[s + 3]);
        }
      }
    }
  }

  const int h = h0 + hh;
  if (h < IH) {
    float b0 = bias[k0g + ty * 4 + 0];
    float b1 = bias[k0g + ty * 4 + 1];
    float b2 = bias[k0g + ty * 4 + 2];
    float b3 = bias[k0g + ty * 4 + 3];
    float2 p0[4] = {unpk(a00), unpk(a01), unpk(a02), unpk(a03)};
    float2 p1[4] = {unpk(a10), unpk(a11), unpk(a12), unpk(a13)};
#pragma unroll
    for (int j = 0; j < 4; ++j) {
      int ww = w0 + wq * 4 + j;
      if (ww < IW) {
        int p = h * IW + ww;
        float4 o;
        o.x = fmaxf(p0[j].x + b0, 0.f);
        o.y = fmaxf(p0[j].y + b1, 0.f);
        o.z = fmaxf(p1[j].x + b2, 0.f);
        o.w = fmaxf(p1[j].y + b3, 0.f);
        *(float4*)(&g_h1T[(size_t)p * 512 + k0g + ty * 4]) = o;
      }
    }
  }
}

// ---------------- 1x1 heads + anchor decode + key build ----------------
__device__ __forceinline__ unsigned f2key(float f) {
  unsigned u = __float_as_uint(f);
  return (u & 0x80000000u) ? ~u : (u | 0x80000000u);
}

__global__ __launch_bounds__(256) void rpn_head(
    const float* __restrict__ loc_w, const float* __restrict__ loc_b,
    const float* __restrict__ score_w, const float* __restrict__ score_b) {
  const int p = blockIdx.x;             // 0..1899
  const int tid = threadIdx.x;
  // fold: zero the bucket histogram for the next kernel
  if (tid < 18) {
    int z = p + tid * 1900;
    if (z < NBUCK) g_hist[z] = 0u;
  }
  __shared__ float sh[512];
  __shared__ float sums[48];            // 36 loc + 9 fg

  ((float2*)sh)[tid] = ((const float2*)(g_h1T + (size_t)p * 512))[tid];
  __syncthreads();

  const int wid = tid >> 5, lane = tid & 31;
  for (int o = wid; o < 45; o += 8) {
    const float* wrow;
    float bb;
    if (o < 36) { wrow = loc_w + (size_t)o * 512; bb = loc_b[o]; }
    else { int a = o - 36; wrow = score_w + (size_t)(2 * a + 1) * 512; bb = score_b[2 * a + 1]; }
    float s = 0.f;
#pragma unroll 4
    for (int c = lane; c < 512; c += 32) s = fmaf(wrow[c], sh[c], s);
#pragma unroll
    for (int off = 16; off; off >>= 1) s += __shfl_down_sync(0xffffffffu, s, off);
    if (lane == 0) sums[o] = s + bb;
  }
  __syncthreads();

  if (tid < 9) {
    const int a = tid;
    float dy = sums[a * 4 + 0], dx = sums[a * 4 + 1];
    float dh = sums[a * 4 + 2], dw = sums[a * 4 + 3];
    float fg = sums[36 + a];
    int h = p / IW, w = p % IW;
    float sy = (float)h * 16.f, sx = (float)w * 16.f;
    float ay0 = __fadd_rn(sy, c_ab[a][0]);
    float ax0 = __fadd_rn(sx, c_ab[a][1]);
    float ay1 = __fadd_rn(sy, c_ab[a][2]);
    float ax1 = __fadd_rn(sx, c_ab[a][3]);
    float ah = __fadd_rn(ay1, -ay0);
    float aw = __fadd_rn(ax1, -ax0);
    float acy = __fadd_rn(ay0, __fmul_rn(0.5f, ah));
    float acx = __fadd_rn(ax0, __fmul_rn(0.5f, aw));
    float cy = __fadd_rn(__fmul_rn(dy, ah), acy);
    float cx = __fadd_rn(__fmul_rn(dx, aw), acx);
    float bh = __fmul_rn(expf(dh), ah);
    float bw = __fmul_rn(expf(dw), aw);
    float y1 = fminf(fmaxf(__fadd_rn(cy, -__fmul_rn(0.5f, bh)), 0.f), 608.f);
    float x1 = fminf(fmaxf(__fadd_rn(cx, -__fmul_rn(0.5f, bw)), 0.f), 800.f);
    float y2 = fminf(fmaxf(__fadd_rn(cy,  __fmul_rn(0.5f, bh)), 0.f), 608.f);
    float x2 = fminf(fmaxf(__fadd_rn(cx,  __fmul_rn(0.5f, bw)), 0.f), 800.f);
    bool valid = (__fadd_rn(y2, -y1) >= 16.f) && (__fadd_rn(x2, -x1) >= 16.f);
    float sc = valid ? fg : -__int_as_float(0x7f800000);

    int i = p * 9 + a;
    g_box[i * 4 + 0] = y1; g_box[i * 4 + 1] = x1;
    g_box[i * 4 + 2] = y2; g_box[i * 4 + 3] = x2;
    g_keys[i] = ((ull)f2key(sc) << 32) | (ull)(~(unsigned)i);
  }
}

// --------- distributed 15-bit bucket histogram (spread gmem atomics) ----
__global__ __launch_bounds__(512) void bucket_hist() {
  int i = blockIdx.x * 512 + threadIdx.x;
  if (i < NANCH)
    atomicAdd(&g_hist[(unsigned)(g_keys[i] >> 49)], 1u);
}

// --------- find bucket threshold (suffix >= 6000) + compact candidates --
__global__ __launch_bounds__(1024) void select_candidates() {
  __shared__ unsigned sp[1024];
  __shared__ int s_B, s_cnt;
  const int tid = threadIdx.x;
  if (tid == 0) s_cnt = 0;

  // per-thread partial over 32 buckets
  unsigned part = 0;
#pragma unroll 4
  for (int b = 0; b < 32; ++b) part += g_hist[tid * 32 + b];
  sp[tid] = part;
  __syncthreads();
  // inclusive suffix sum over 1024 (Hillis-Steele)
  for (int d = 1; d < 1024; d <<= 1) {
    unsigned v = (tid + d < 1024) ? sp[tid + d] : 0u;
    __syncthreads();
    sp[tid] += v;
    __syncthreads();
  }
  // find chunk t*: sp[t*] >= 6000 > sp[t*+1]
  unsigned nxt = (tid + 1 < 1024) ? sp[tid + 1] : 0u;
  if (sp[tid] >= PRE_N && nxt < PRE_N) {
    // walk 32 buckets of this chunk from the top
    unsigned running = nxt;
    for (int b = tid * 32 + 31; b >= tid * 32; --b) {
      running += g_hist[b];
      if (running >= PRE_N) { s_B = b; break; }
    }
  }
  __syncthreads();
  const unsigned B = (unsigned)s_B;

  // compact all keys with bucket >= B (superset of top-6000, ~6000+eps)
  for (int i = tid; i < NANCH; i += 1024) {
    ull k = g_keys[i];
    if ((unsigned)(k >> 49) >= B) {
      int pos = atomicAdd(&s_cnt, 1);
      if (pos < NSEL) g_sel[pos] = k;
    }
  }
  __syncthreads();
  for (int i = s_cnt + tid; i < NSEL; i += 1024) g_sel[i] = 0ull;
}

// ------- bitonic local sort of 4096 (barrier only when j >= 64) ---------
__global__ __launch_bounds__(1024) void bitonic_local_sort() {
  __shared__ ull s[4096];
  const int base = blockIdx.x * 4096;
  const int t = threadIdx.x;
  // own-span load: s[4t..4t+3]
  {
    ulonglong2 v0 = ((const ulonglong2*)(g_sel + base))[t * 2];
    ulonglong2 v1 = ((const ulonglong2*)(g_sel + base))[t * 2 + 1];
    ((ulonglong2*)s)[t * 2]     = v0;
    ((ulonglong2*)s)[t * 2 + 1] = v1;
  }
  __syncthreads();

  for (int k = 2; k <= 4096; k <<= 1) {
    for (int j = k >> 1; j > 0; j >>= 1) {
      if (j >= 64) __syncthreads(); else __syncwarp();
#pragma unroll
      for (int m = 0; m < 2; ++m) {
        int p = t * 2 + m;
        int i = ((p & ~(j - 1)) << 1) | (p & (j - 1));
        int ix = i | j;
        bool desc = (((base + i) & k) == 0);
        ull a = s[i], b = s[ix];
        if (desc ? (a < b) : (a > b)) { s[i] = b; s[ix] = a; }
      }
    }
  }
  __syncthreads();
  ((ulonglong2*)(g_sel + base))[t * 2]     = ((ulonglong2*)s)[t * 2];
  ((ulonglong2*)(g_sel + base))[t * 2 + 1] = ((ulonglong2*)s)[t * 2 + 1];
}

// ------- merge 8192 (j=4096..1, desc) + gather + validity epilogue ------
__global__ __launch_bounds__(1024) void merge_tail_gather() {
  extern __shared__ ull s[];
  const int t = threadIdx.x;
#pragma unroll
  for (int m = 0; m < 4; ++m)
    ((ulonglong2*)s)[t * 4 + m] = ((const ulonglong2*)g_sel)[t * 4 + m];
  __syncthreads();

  for (int j = 4096; j > 0; j >>= 1) {
    if (j >= 128) __syncthreads(); else __syncwarp();
#pragma unroll
    for (int m = 0; m < 4; ++m) {
      int p = t * 4 + m;
      int i = ((p & ~(j - 1)) << 1) | (p & (j - 1));
      int ix = i | j;
      ull a = s[i], b = s[ix];
      if (a < b) { s[i] = b; s[ix] = a; }    // k=8192: all descending
    }
  }
  __syncthreads();

  // epilogue: gather boxes + validity ballots
#pragma unroll
  for (int m = 0; m < 8; ++m) {
    int e = t + m * 1024;
    ull key = s[e];
    bool valid = (e < PRE_N) && ((unsigned)(key >> 32) > 0x007FFFFFu);
    unsigned bal = __ballot_sync(0xffffffffu, valid);
    if ((e & 31) == 0) ((unsigned*)g_validw)[e >> 5] = bal;
    if (e < PRE_N) {
      unsigned idx = ~(unsigned)(key & 0xffffffffull);
      float4 b = make_float4(0.f, 0.f, 0.f, 0.f);
      if (idx < NANCH) b = ((const float4*)g_box)[idx];
      ((float4*)g_tb)[e] = b;
    }
  }
}

// ---------------- NMS suppression-mask matrix (upper triangle) ----------
__global__ __launch_bounds__(64) void nms_mask() {
  const int cb = blockIdx.x;
  const int rb = blockIdx.y;
  if (cb < rb) return;
  const int tid = threadIdx.x;
  __shared__ float4 colb[64];
  __shared__ float cola[64];
  int j0 = cb * 64;
  int jj = j0 + tid;
  float4 b = (jj < PRE_N) ? ((const float4*)g_tb)[jj] : make_float4(0.f,0.f,0.f,0.f);
  colb[tid] = b;
  cola[tid] = __fmul_rn(__fadd_rn(b.z, -b.x), __fadd_rn(b.w, -b.y));
  __syncthreads();
  int i = rb * 64 + tid;
  if (i >= PRE_N) return;
  float4 r = ((const float4*)g_tb)[i];
  float ra = __fmul_rn(__fadd_rn(r.z, -r.x), __fadd_rn(r.w, -r.y));
  ull bits = 0ull;
  int jmax = min(64, PRE_N - j0);
  for (int q = 0; q < jmax; ++q) {
    int j = j0 + q;
    if (j <= i) continue;
    float4 c = colb[q];
    float ty1 = fmaxf(r.x, c.x);
    float tx1 = fmaxf(r.y, c.y);
    float ty2 = fminf(r.z, c.z);
    float tx2 = fminf(r.w, c.w);
    float ihh = fmaxf(__fadd_rn(ty2, -ty1), 0.f);
    float iww = fmaxf(__fadd_rn(tx2, -tx1), 0.f);
    float inter = __fmul_rn(ihh, iww);
    float uni = fmaxf(__fadd_rn(__fadd_rn(ra, cola[q]), -inter), 1e-9f);
    float rhs = 0.7f * uni;
    bool sup;
    if (inter > rhs * 1.00001f)       sup = true;
    else if (inter < rhs * 0.99999f)  sup = false;
    else sup = (__fdiv_rn(inter, uni) > 0.7f);
    if (sup) bits |= (1ull << q);
  }
  g_mask[(size_t)i * MASKW + cb] = bits;
}

// ---------- sequential NMS scan: ffs bit-walk over alive set ------------
__global__ __launch_bounds__(256) void nms_scan(float* __restrict__ out) {
  __shared__ ull remv[MASKW];
  __shared__ int keptIdx[POST_N];
  __shared__ int wordKept[64];
  __shared__ int s_nk, s_nwk;
  const int tid = threadIdx.x;
  if (tid < MASKW) remv[tid] = 0ull;
  if (tid == 0) s_nk = 0;
  for (int i = tid; i < POST_N * 4; i += 256) out[i] = 0.f;
  __syncthreads();

  for (int w = 0; w < MASKW; ++w) {
    if (tid < 32) {
      ull vw = ((const ull*)g_validw)[w];
      ull alive = vw & ~remv[w];
      int base = w * 64;
      ull mA = ((alive >> tid) & 1ull) ? g_mask[(size_t)(base + tid) * MASKW + w] : 0ull;
      ull mB = ((alive >> (tid + 32)) & 1ull) ? g_mask[(size_t)(base + tid + 32) * MASKW + w] : 0ull;
      int nk = s_nk, nwk = 0;
      while (alive && nk < POST_N) {
        int q = __ffsll((long long)alive) - 1;
        ull mq = (q < 32) ? __shfl_sync(0xffffffffu, mA, q)
                          : __shfl_sync(0xffffffffu, mB, q - 32);
        if (tid == 0) { keptIdx[nk] = base + q; wordKept[nwk] = base + q; }
        ++nk; ++nwk;
        alive &= ~((1ull << q) | mq);
      }
      if (tid == 0) { s_nk = nk; s_nwk = nwk; }
    }
    __syncthreads();
    for (int r = 0; r < s_nwk; ++r) {
      int i = wordKept[r];
      if (tid < MASKW) remv[tid] |= g_mask[(size_t)i * MASKW + tid];
    }
    __syncthreads();
    if (s_nk >= POST_N) break;
  }

  __syncthreads();
  for (int r = tid; r < s_nk; r += 256)
    ((float4*)out)[r] = ((const float4*)g_tb)[keptIdx[r]];
}

// ---------------- launcher ----------------
extern "C" void kernel_launch(void* const* d_in, const int* in_sizes, int n_in,
                              void* d_out, int out_size) {
  const float* x        = (const float*)d_in[0];
  const float* conv1_w  = (const float*)d_in[1];
  const float* conv1_b  = (const float*)d_in[2];
  const float* loc_w    = (const float*)d_in[3];
  const float* loc_b    = (const float*)d_in[4];
  const float* score_w  = (const float*)d_in[5];
  const float* score_b  = (const float*)d_in[6];
  float* out = (float*)d_out;

  static bool attr_done = false;
  if (!attr_done) {
    cudaFuncSetAttribute(merge_tail_gather,
                         cudaFuncAttributeMaxDynamicSharedMemorySize, 65536);
    attr_done = true;
  }

  dim3 cgrid(7, 5, 8);
  conv3x3_relu<<<cgrid, 256>>>(x, conv1_w, conv1_b);
  rpn_head<<<HWPIX, 256>>>(loc_w, loc_b, score_w, score_b);
  bucket_hist<<<(NANCH + 511) / 512, 512>>>();
  select_candidates<<<1, 1024>>>();
  bitonic_local_sort<<<2, 1024>>>();
  merge_tail_gather<<<1, 1024, 65536>>>();
  nms_mask<<<dim3(MASKW, MASKW), 64>>>();
  nms_scan<<<1, 256>>>(out);
}

// round 5
// speedup vs baseline: 1.0140x; 1.0140x over previous
#include <cuda_runtime.h>

#define C_IN   512
#define IH     38
#define IW     50
#define HWPIX  1900
#define NANCH  17100
#define NSORT  32768
#define PRE_N  6000
#define POST_N 300
#define MASKW  94        // ceil(6000/64)

typedef unsigned long long ull;

// ---------------- device scratch (static, no allocation) ----------------
__device__ float g_h1T[HWPIX * 512];                   // conv output, [pixel][k]
__device__ float g_box[NANCH * 4];                     // decoded clipped boxes
__device__ ull   g_keys[NSORT];                        // (score<<32)|~idx
__device__ float g_tb[PRE_N * 4];                      // top-6000 boxes (sorted)
__device__ ull   g_mask[(size_t)PRE_N * MASKW];        // lower tri never written
__device__ ull   g_validw[128];                        // validity bits of top-6000

__constant__ float c_ab[9][4] = {
  {-37.254833f,  -82.50967f,   53.254833f,  98.50967f},
  {-82.50967f,  -173.01933f,   98.50967f,  189.01933f},
  {-173.01933f, -354.03867f,  189.01933f,  370.03867f},
  {-56.0f,       -56.0f,        72.0f,       72.0f},
  {-120.0f,     -120.0f,       136.0f,      136.0f},
  {-248.0f,     -248.0f,       264.0f,      264.0f},
  {-82.50967f,   -37.254833f,  98.50967f,   53.254833f},
  {-173.01933f,  -82.50967f,  189.01933f,   98.50967f},
  {-354.03867f, -173.01933f,  370.03867f,  189.01933f}};

// ---------------- f32x2 helpers ----------------
__device__ __forceinline__ ull dup2(float v) {
  ull r; asm("mov.b64 %0, {%1, %1};" : "=l"(r) : "f"(v)); return r;
}
__device__ __forceinline__ void fma2(ull& d, ull a, ull b) {
  asm("fma.rn.f32x2 %0, %1, %2, %0;" : "+l"(d) : "l"(a), "l"(b));
}
__device__ __forceinline__ float2 unpk(ull v) {
  float2 f; asm("mov.b64 {%0, %1}, %2;" : "=f"(f.x), "=f"(f.y) : "l"(v)); return f;
}

// ---------------- 3x3 conv + bias + relu -> g_h1T[p][k] ----------------
__global__ __launch_bounds__(256) void conv3x3_relu(
    const float* __restrict__ x, const float* __restrict__ wgt,
    const float* __restrict__ bias) {
  const int wt = blockIdx.x;            // 0..6
  const int ht = blockIdx.y;            // 0..4
  const int kt = blockIdx.z;            // 0..7
  const int h0 = ht * 8, w0 = wt * 8;
  const int tid = threadIdx.x;
  const int ty  = tid >> 4;             // 0..15 (k groups of 4)
  const int txp = tid & 15;
  const int hh  = txp >> 1;             // 0..7
  const int wq  = txp & 1;              // 0..1 (w groups of 4)

  __shared__ float sW[72 * 66];                     // [crs][k], stride 66
  __shared__ __align__(16) float sX[8][10][12];     // [c][row][col]

  ull a00 = 0, a01 = 0, a02 = 0, a03 = 0;
  ull a10 = 0, a11 = 0, a12 = 0, a13 = 0;

  const int k0g = kt * 64;

  for (int c0 = 0; c0 < C_IN; c0 += 8) {
    __syncthreads();
#pragma unroll
    for (int l = 0; l < 18; ++l) {
      int idx = tid + l * 256;          // = k*72 + crs
      int k = idx / 72, crs = idx % 72;
      sW[crs * 66 + k] = wgt[(size_t)(k0g + k) * 4608 + (size_t)c0 * 9 + crs];
    }
    for (int idx = tid; idx < 800; idx += 256) {
      int c = idx / 100, rem = idx % 100;
      int row = rem / 10, col = rem % 10;
      int gh = h0 - 1 + row, gw = w0 - 1 + col;
      float v = 0.f;
      if (gh >= 0 && gh < IH && gw >= 0 && gw < IW)
        v = x[(size_t)(c0 + c) * HWPIX + gh * IW + gw];
      sX[c][row][col] = v;
    }
    __syncthreads();

#pragma unroll 2
    for (int c = 0; c < 8; ++c) {
#pragma unroll
      for (int r = 0; r < 3; ++r) {
        const float* xp = &sX[c][hh + r][wq * 4];
        float4 xa = *(const float4*)xp;
        float2 xb = *(const float2*)(xp + 4);
        ull xd[6] = {dup2(xa.x), dup2(xa.y), dup2(xa.z),
                     dup2(xa.w), dup2(xb.x), dup2(xb.y)};
#pragma unroll
        for (int s = 0; s < 3; ++s) {
          int wi = (c * 9 + r * 3 + s) * 66 + ty * 4;
          ull w01 = *(const ull*)&sW[wi];
          ull w23 = *(const ull*)&sW[wi + 2];
          fma2(a00, w01, xd[s + 0]);
          fma2(a01, w01, xd[s + 1]);
          fma2(a02, w01, xd[s + 2]);
          fma2(a03, w01, xd[s + 3]);
          fma2(a10, w23, xd[s + 0]);
          fma2(a11, w23, xd[s + 1]);
          fma2(a12, w23, xd[s + 2]);
          fma2(a13, w23, xd[s + 3]);
        }
      }
    }
  }

  const int h = h0 + hh;
  if (h < IH) {
    float b0 = bias[k0g + ty * 4 + 0];
    float b1 = bias[k0g + ty * 4 + 1];
    float b2 = bias[k0g + ty * 4 + 2];
    float b3 = bias[k0g + ty * 4 + 3];
    float2 p0[4] = {unpk(a00), unpk(a01), unpk(a02), unpk(a03)};
    float2 p1[4] = {unpk(a10), unpk(a11), unpk(a12), unpk(a13)};
#pragma unroll
    for (int j = 0; j < 4; ++j) {
      int ww = w0 + wq * 4 + j;
      if (ww < IW) {
        int p = h * IW + ww;
        float4 o;
        o.x = fmaxf(p0[j].x + b0, 0.f);
        o.y = fmaxf(p0[j].y + b1, 0.f);
        o.z = fmaxf(p1[j].x + b2, 0.f);
        o.w = fmaxf(p1[j].y + b3, 0.f);
        *(float4*)(&g_h1T[(size_t)p * 512 + k0g + ty * 4]) = o;
      }
    }
  }
}

// ---------------- 1x1 heads + anchor decode + key build (+pad) ----------
__device__ __forceinline__ unsigned f2key(float f) {
  unsigned u = __float_as_uint(f);
  return (u & 0x80000000u) ? ~u : (u | 0x80000000u);
}

__global__ __launch_bounds__(256) void rpn_head(
    const float* __restrict__ loc_w, const float* __restrict__ loc_b,
    const float* __restrict__ score_w, const float* __restrict__ score_b) {
  const int p = blockIdx.x;             // 0..1899 compute; >=1900 pad keys
  const int tid = threadIdx.x;
  if (p >= HWPIX) {
    int i = NANCH + (p - HWPIX) * 256 + tid;
    if (i < NSORT) g_keys[i] = 0ull;
    return;
  }
  __shared__ float sh[512];
  __shared__ float sums[48];            // 36 loc + 9 fg

  ((float2*)sh)[tid] = ((const float2*)(g_h1T + (size_t)p * 512))[tid];
  __syncthreads();

  const int wid = tid >> 5, lane = tid & 31;
  for (int o = wid; o < 45; o += 8) {
    const float* wrow;
    float bb;
    if (o < 36) { wrow = loc_w + (size_t)o * 512; bb = loc_b[o]; }
    else { int a = o - 36; wrow = score_w + (size_t)(2 * a + 1) * 512; bb = score_b[2 * a + 1]; }
    float s = 0.f;
#pragma unroll 4
    for (int c = lane; c < 512; c += 32) s = fmaf(wrow[c], sh[c], s);
#pragma unroll
    for (int off = 16; off; off >>= 1) s += __shfl_down_sync(0xffffffffu, s, off);
    if (lane == 0) sums[o] = s + bb;
  }
  __syncthreads();

  if (tid < 9) {
    const int a = tid;
    float dy = sums[a * 4 + 0], dx = sums[a * 4 + 1];
    float dh = sums[a * 4 + 2], dw = sums[a * 4 + 3];
    float fg = sums[36 + a];
    int h = p / IW, w = p % IW;
    float sy = (float)h * 16.f, sx = (float)w * 16.f;
    float ay0 = __fadd_rn(sy, c_ab[a][0]);
    float ax0 = __fadd_rn(sx, c_ab[a][1]);
    float ay1 = __fadd_rn(sy, c_ab[a][2]);
    float ax1 = __fadd_rn(sx, c_ab[a][3]);
    float ah = __fadd_rn(ay1, -ay0);
    float aw = __fadd_rn(ax1, -ax0);
    float acy = __fadd_rn(ay0, __fmul_rn(0.5f, ah));
    float acx = __fadd_rn(ax0, __fmul_rn(0.5f, aw));
    float cy = __fadd_rn(__fmul_rn(dy, ah), acy);
    float cx = __fadd_rn(__fmul_rn(dx, aw), acx);
    float bh = __fmul_rn(expf(dh), ah);
    float bw = __fmul_rn(expf(dw), aw);
    float y1 = fminf(fmaxf(__fadd_rn(cy, -__fmul_rn(0.5f, bh)), 0.f), 608.f);
    float x1 = fminf(fmaxf(__fadd_rn(cx, -__fmul_rn(0.5f, bw)), 0.f), 800.f);
    float y2 = fminf(fmaxf(__fadd_rn(cy,  __fmul_rn(0.5f, bh)), 0.f), 608.f);
    float x2 = fminf(fmaxf(__fadd_rn(cx,  __fmul_rn(0.5f, bw)), 0.f), 800.f);
    bool valid = (__fadd_rn(y2, -y1) >= 16.f) && (__fadd_rn(x2, -x1) >= 16.f);
    float sc = valid ? fg : -__int_as_float(0x7f800000);

    int i = p * 9 + a;
    g_box[i * 4 + 0] = y1; g_box[i * 4 + 1] = x1;
    g_box[i * 4 + 2] = y2; g_box[i * 4 + 3] = x2;
    g_keys[i] = ((ull)f2key(sc) << 32) | (ull)(~(unsigned)i);
  }
}

// ------ bitonic local sort of 4096 (syncwarp when j<64), 8 blocks -------
__global__ __launch_bounds__(1024) void bitonic_local_sort() {
  __shared__ ull s[4096];
  const int base = blockIdx.x * 4096;
  const int t = threadIdx.x;
  ((ulonglong2*)s)[t * 2]     = ((const ulonglong2*)(g_keys + base))[t * 2];
  ((ulonglong2*)s)[t * 2 + 1] = ((const ulonglong2*)(g_keys + base))[t * 2 + 1];
  __syncthreads();

  for (int k = 2; k <= 4096; k <<= 1) {
    for (int j = k >> 1; j > 0; j >>= 1) {
      if (j >= 64) __syncthreads(); else __syncwarp();
#pragma unroll
      for (int m = 0; m < 2; ++m) {
        int p = t * 2 + m;
        int i = ((p & ~(j - 1)) << 1) | (p & (j - 1));
        int ix = i | j;
        bool desc = (((base + i) & k) == 0);
        ull a = s[i], b = s[ix];
        if (desc ? (a < b) : (a > b)) { s[i] = b; s[ix] = a; }
      }
    }
  }
  __syncthreads();
  ((ulonglong2*)(g_keys + base))[t * 2]     = ((ulonglong2*)s)[t * 2];
  ((ulonglong2*)(g_keys + base))[t * 2 + 1] = ((ulonglong2*)s)[t * 2 + 1];
}

// ---------------- global bitonic stage (j >= 4096) ----------------------
__global__ void bitonic_global(int k, int j) {
  int t = blockIdx.x * blockDim.x + threadIdx.x;   // 16384 threads
  int i = ((t & ~(j - 1)) << 1) | (t & (j - 1));
  int ix = i | j;
  bool desc = ((i & k) == 0);
  ull a = g_keys[i], b = g_keys[ix];
  if (desc ? (a < b) : (a > b)) { g_keys[i] = b; g_keys[ix] = a; }
}

// ------ local tail j=2048..1 (syncwarp when j<64), 8 blocks -------------
__global__ __launch_bounds__(1024) void bitonic_tail(int k) {
  __shared__ ull s[4096];
  const int base = blockIdx.x * 4096;
  const int t = threadIdx.x;
  ((ulonglong2*)s)[t * 2]     = ((const ulonglong2*)(g_keys + base))[t * 2];
  ((ulonglong2*)s)[t * 2 + 1] = ((const ulonglong2*)(g_keys + base))[t * 2 + 1];
  __syncthreads();

  for (int j = 2048; j > 0; j >>= 1) {
    if (j >= 64) { if (j < 2048) __syncthreads(); } else __syncwarp();
#pragma unroll
    for (int m = 0; m < 2; ++m) {
      int p = t * 2 + m;
      int i = ((p & ~(j - 1)) << 1) | (p & (j - 1));
      int ix = i | j;
      bool desc = (((base + i) & k) == 0);
      ull a = s[i], b = s[ix];
      if (desc ? (a < b) : (a > b)) { s[i] = b; s[ix] = a; }
    }
  }
  __syncthreads();
  ((ulonglong2*)(g_keys + base))[t * 2]     = ((ulonglong2*)s)[t * 2];
  ((ulonglong2*)(g_keys + base))[t * 2 + 1] = ((ulonglong2*)s)[t * 2 + 1];
}

// ------ final tail (k=32768, all desc) + gather/validity epilogue -------
__global__ __launch_bounds__(1024) void bitonic_tail_final() {
  __shared__ ull s[4096];
  const int base = blockIdx.x * 4096;
  const int t = threadIdx.x;
  ((ulonglong2*)s)[t * 2]     = ((const ulonglong2*)(g_keys + base))[t * 2];
  ((ulonglong2*)s)[t * 2 + 1] = ((const ulonglong2*)(g_keys + base))[t * 2 + 1];
  __syncthreads();

  for (int j = 2048; j > 0; j >>= 1) {
    if (j >= 64) { if (j < 2048) __syncthreads(); } else __syncwarp();
#pragma unroll
    for (int m = 0; m < 2; ++m) {
      int p = t * 2 + m;
      int i = ((p & ~(j - 1)) << 1) | (p & (j - 1));
      int ix = i | j;
      ull a = s[i], b = s[ix];
      if (a < b) { s[i] = b; s[ix] = a; }   // k=32768: all descending
    }
  }
  __syncthreads();
  // epilogue: only elements < PRE_N matter downstream
#pragma unroll
  for (int m = 0; m < 4; ++m) {
    int e = base + t + m * 1024;
    ull key = s[t + m * 1024];
    g_keys[e] = key;
    if (e < 6144) {
      bool valid = (e < PRE_N) && ((unsigned)(key >> 32) > 0x007FFFFFu);
      unsigned bal = __ballot_sync(0xffffffffu, valid);
      if ((e & 31) == 0) ((unsigned*)g_validw)[e >> 5] = bal;
      if (e < PRE_N) {
        unsigned idx = ~(unsigned)(key & 0xffffffffull);
        float4 b = make_float4(0.f, 0.f, 0.f, 0.f);
        if (idx < NANCH) b = ((const float4*)g_box)[idx];
        ((float4*)g_tb)[e] = b;
      }
    }
  }
}

// ---------------- NMS suppression-mask matrix (upper triangle) ----------
__global__ __launch_bounds__(64) void nms_mask() {
  const int cb = blockIdx.x;
  const int rb = blockIdx.y;
  if (cb < rb) return;
  const int tid = threadIdx.x;
  __shared__ float4 colb[64];
  __shared__ float cola[64];
  int j0 = cb * 64;
  int jj = j0 + tid;
  float4 b = (jj < PRE_N) ? ((const float4*)g_tb)[jj] : make_float4(0.f,0.f,0.f,0.f);
  colb[tid] = b;
  cola[tid] = __fmul_rn(__fadd_rn(b.z, -b.x), __fadd_rn(b.w, -b.y));
  __syncthreads();
  int i = rb * 64 + tid;
  if (i >= PRE_N) return;
  float4 r = ((const float4*)g_tb)[i];
  float ra = __fmul_rn(__fadd_rn(r.z, -r.x), __fadd_rn(r.w, -r.y));
  ull bits = 0ull;
  int jmax = min(64, PRE_N - j0);
  for (int q = 0; q < jmax; ++q) {
    int j = j0 + q;
    if (j <= i) continue;
    float4 c = colb[q];
    float ty1 = fmaxf(r.x, c.x);
    float tx1 = fmaxf(r.y, c.y);
    float ty2 = fminf(r.z, c.z);
    float tx2 = fminf(r.w, c.w);
    float ihh = fmaxf(__fadd_rn(ty2, -ty1), 0.f);
    float iww = fmaxf(__fadd_rn(tx2, -tx1), 0.f);
    float inter = __fmul_rn(ihh, iww);
    float uni = fmaxf(__fadd_rn(__fadd_rn(ra, cola[q]), -inter), 1e-9f);
    float rhs = 0.7f * uni;
    bool sup;
    if (inter > rhs * 1.00001f)       sup = true;
    else if (inter < rhs * 0.99999f)  sup = false;
    else sup = (__fdiv_rn(inter, uni) > 0.7f);
    if (sup) bits |= (1ull << q);
  }
  g_mask[(size_t)i * MASKW + cb] = bits;
}

// ---- NMS scan: ffs bit-walk + PARALLEL row fold, early stop @300 -------
__global__ __launch_bounds__(256) void nms_scan(float* __restrict__ out) {
  __shared__ ull remv[MASKW];
  __shared__ int keptIdx[POST_N];
  __shared__ int wordKept[64];
  __shared__ int s_nk, s_nwk;
  const int tid = threadIdx.x;
  if (tid < MASKW) remv[tid] = 0ull;
  if (tid == 0) s_nk = 0;
  for (int i = tid; i < POST_N * 4; i += 256) out[i] = 0.f;
  __syncthreads();

  for (int w = 0; w < MASKW; ++w) {
    if (tid < 32) {
      ull vw = ((const ull*)g_validw)[w];
      ull alive = vw & ~remv[w];
      int base = w * 64;
      // prefetch diagonal mask words of alive candidates
      ull mA = ((alive >> tid) & 1ull) ? g_mask[(size_t)(base + tid) * MASKW + w] : 0ull;
      ull mB = ((alive >> (tid + 32)) & 1ull) ? g_mask[(size_t)(base + tid + 32) * MASKW + w] : 0ull;
      int nk = s_nk, nwk = 0;
      while (alive && nk < POST_N) {
        int q = __ffsll((long long)alive) - 1;
        ull mq = (q < 32) ? __shfl_sync(0xffffffffu, mA, q)
                          : __shfl_sync(0xffffffffu, mB, q - 32);
        if (tid == 0) { keptIdx[nk] = base + q; wordKept[nwk] = base + q; }
        ++nk; ++nwk;
        alive &= ~((1ull << q) | mq);
      }
      if (tid == 0) { s_nk = nk; s_nwk = nwk; }
    }
    __syncthreads();
    // parallel fold: all (kept r x word wd) loads issue concurrently
    int total = s_nwk * MASKW;
    for (int e = tid; e < total; e += 256) {
      int r = e / MASKW, wd = e - r * MASKW;
      ull m = g_mask[(size_t)wordKept[r] * MASKW + wd];
      if (m) atomicOr(&remv[wd], m);
    }
    __syncthreads();
    if (s_nk >= POST_N) break;
  }

  __syncthreads();
  for (int r = tid; r < s_nk; r += 256)
    ((float4*)out)[r] = ((const float4*)g_tb)[keptIdx[r]];
}

// ---------------- launcher ----------------
extern "C" void kernel_launch(void* const* d_in, const int* in_sizes, int n_in,
                              void* d_out, int out_size) {
  const float* x        = (const float*)d_in[0];
  const float* conv1_w  = (const float*)d_in[1];
  const float* conv1_b  = (const float*)d_in[2];
  const float* loc_w    = (const float*)d_in[3];
  const float* loc_b    = (const float*)d_in[4];
  const float* score_w  = (const float*)d_in[5];
  const float* score_b  = (const float*)d_in[6];
  float* out = (float*)d_out;

  dim3 cgrid(7, 5, 8);
  conv3x3_relu<<<cgrid, 256>>>(x, conv1_w, conv1_b);
  rpn_head<<<HWPIX + 62, 256>>>(loc_w, loc_b, score_w, score_b);

  bitonic_local_sort<<<8, 1024>>>();
  bitonic_global<<<64, 256>>>(8192, 4096);
  bitonic_tail<<<8, 1024>>>(8192);
  bitonic_global<<<64, 256>>>(16384, 8192);
  bitonic_global<<<64, 256>>>(16384, 4096);
  bitonic_tail<<<8, 1024>>>(16384);
  bitonic_global<<<64, 256>>>(32768, 16384);
  bitonic_global<<<64, 256>>>(32768, 8192);
  bitonic_global<<<64, 256>>>(32768, 4096);
  bitonic_tail_final<<<8, 1024>>>();

  nms_mask<<<dim3(MASKW, MASKW), 64>>>();
  nms_scan<<<1, 256>>>(out);
}

// round 6
// speedup vs baseline: 1.0741x; 1.0592x over previous
#include <cuda_runtime.h>

#define C_IN   512
#define IH     38
#define IW     50
#define HWPIX  1900
#define NANCH  17100
#define NSORT  32768
#define PRE_N  6000
#define POST_N 300
#define MASKW  94        // ceil(6000/64)

typedef unsigned long long ull;

// ---------------- device scratch (static, no allocation) ----------------
__device__ float    g_h1T[HWPIX * 512];                // conv output, [pixel][k]
__device__ float    g_box[NANCH * 4];                  // decoded clipped boxes
__device__ ull      g_keys[NSORT];                     // ping buffer
__device__ ull      g_keys2[NSORT];                    // pong buffer
__device__ float    g_tb[PRE_N * 4];                   // top-6000 boxes (sorted)
__device__ ull      g_mask[(size_t)PRE_N * MASKW];     // lower tri never written
__device__ ull      g_validw[96];                      // validity bits of top-6000
__device__ unsigned g_bar;                             // grid spin barrier

__constant__ float c_ab[9][4] = {
  {-37.254833f,  -82.50967f,   53.254833f,  98.50967f},
  {-82.50967f,  -173.01933f,   98.50967f,  189.01933f},
  {-173.01933f, -354.03867f,  189.01933f,  370.03867f},
  {-56.0f,       -56.0f,        72.0f,       72.0f},
  {-120.0f,     -120.0f,       136.0f,      136.0f},
  {-248.0f,     -248.0f,       264.0f,      264.0f},
  {-82.50967f,   -37.254833f,  98.50967f,   53.254833f},
  {-173.01933f,  -82.50967f,  189.01933f,   98.50967f},
  {-354.03867f, -173.01933f,  370.03867f,  189.01933f}};

// ---------------- f32x2 helpers ----------------
__device__ __forceinline__ ull dup2(float v) {
  ull r; asm("mov.b64 %0, {%1, %1};" : "=l"(r) : "f"(v)); return r;
}
__device__ __forceinline__ void fma2(ull& d, ull a, ull b) {
  asm("fma.rn.f32x2 %0, %1, %2, %0;" : "+l"(d) : "l"(a), "l"(b));
}
__device__ __forceinline__ float2 unpk(ull v) {
  float2 f; asm("mov.b64 {%0, %1}, %2;" : "=f"(f.x), "=f"(f.y) : "l"(v)); return f;
}

// ---------------- 3x3 conv + bias + relu -> g_h1T[p][k] ----------------
__global__ __launch_bounds__(256) void conv3x3_relu(
    const float* __restrict__ x, const float* __restrict__ wgt,
    const float* __restrict__ bias) {
  const int wt = blockIdx.x;            // 0..6
  const int ht = blockIdx.y;            // 0..4
  const int kt = blockIdx.z;            // 0..7
  const int h0 = ht * 8, w0 = wt * 8;
  const int tid = threadIdx.x;
  const int ty  = tid >> 4;             // 0..15 (k groups of 4)
  const int txp = tid & 15;
  const int hh  = txp >> 1;             // 0..7
  const int wq  = txp & 1;              // 0..1 (w groups of 4)

  __shared__ float sW[72 * 66];                     // [crs][k], stride 66
  __shared__ __align__(16) float sX[8][10][12];     // [c][row][col]

  ull a00 = 0, a01 = 0, a02 = 0, a03 = 0;
  ull a10 = 0, a11 = 0, a12 = 0, a13 = 0;

  const int k0g = kt * 64;

  for (int c0 = 0; c0 < C_IN; c0 += 8) {
    __syncthreads();
#pragma unroll
    for (int l = 0; l < 18; ++l) {
      int idx = tid + l * 256;          // = k*72 + crs
      int k = idx / 72, crs = idx % 72;
      sW[crs * 66 + k] = wgt[(size_t)(k0g + k) * 4608 + (size_t)c0 * 9 + crs];
    }
    for (int idx = tid; idx < 800; idx += 256) {
      int c = idx / 100, rem = idx % 100;
      int row = rem / 10, col = rem % 10;
      int gh = h0 - 1 + row, gw = w0 - 1 + col;
      float v = 0.f;
      if (gh >= 0 && gh < IH && gw >= 0 && gw < IW)
        v = x[(size_t)(c0 + c) * HWPIX + gh * IW + gw];
      sX[c][row][col] = v;
    }
    __syncthreads();

#pragma unroll 2
    for (int c = 0; c < 8; ++c) {
#pragma unroll
      for (int r = 0; r < 3; ++r) {
        const float* xp = &sX[c][hh + r][wq * 4];
        float4 xa = *(const float4*)xp;
        float2 xb = *(const float2*)(xp + 4);
        ull xd[6] = {dup2(xa.x), dup2(xa.y), dup2(xa.z),
                     dup2(xa.w), dup2(xb.x), dup2(xb.y)};
#pragma unroll
        for (int s = 0; s < 3; ++s) {
          int wi = (c * 9 + r * 3 + s) * 66 + ty * 4;
          ull w01 = *(const ull*)&sW[wi];
          ull w23 = *(const ull*)&sW[wi + 2];
          fma2(a00, w01, xd[s + 0]);
          fma2(a01, w01, xd[s + 1]);
          fma2(a02, w01, xd[s + 2]);
          fma2(a03, w01, xd[s + 3]);
          fma2(a10, w23, xd[s + 0]);
          fma2(a11, w23, xd[s + 1]);
          fma2(a12, w23, xd[s + 2]);
          fma2(a13, w23, xd[s + 3]);
        }
      }
    }
  }

  const int h = h0 + hh;
  if (h < IH) {
    float b0 = bias[k0g + ty * 4 + 0];
    float b1 = bias[k0g + ty * 4 + 1];
    float b2 = bias[k0g + ty * 4 + 2];
    float b3 = bias[k0g + ty * 4 + 3];
    float2 p0[4] = {unpk(a00), unpk(a01), unpk(a02), unpk(a03)};
    float2 p1[4] = {unpk(a10), unpk(a11), unpk(a12), unpk(a13)};
#pragma unroll
    for (int j = 0; j < 4; ++j) {
      int ww = w0 + wq * 4 + j;
      if (ww < IW) {
        int p = h * IW + ww;
        float4 o;
        o.x = fmaxf(p0[j].x + b0, 0.f);
        o.y = fmaxf(p0[j].y + b1, 0.f);
        o.z = fmaxf(p1[j].x + b2, 0.f);
        o.w = fmaxf(p1[j].y + b3, 0.f);
        *(float4*)(&g_h1T[(size_t)p * 512 + k0g + ty * 4]) = o;
      }
    }
  }
}

// ---------------- 1x1 heads + anchor decode + key build ----------------
__device__ __forceinline__ unsigned f2key(float f) {
  unsigned u = __float_as_uint(f);
  return (u & 0x80000000u) ? ~u : (u | 0x80000000u);
}

__global__ __launch_bounds__(256) void rpn_head(
    const float* __restrict__ loc_w, const float* __restrict__ loc_b,
    const float* __restrict__ score_w, const float* __restrict__ score_b) {
  const int p = blockIdx.x;             // 0..1899
  const int tid = threadIdx.x;
  if (p == 0 && tid == 0) g_bar = 0u;   // reset grid barrier for fused_sort
  __shared__ float sh[512];
  __shared__ float sums[48];            // 36 loc + 9 fg

  ((float2*)sh)[tid] = ((const float2*)(g_h1T + (size_t)p * 512))[tid];
  __syncthreads();

  const int wid = tid >> 5, lane = tid & 31;
  for (int o = wid; o < 45; o += 8) {
    const float* wrow;
    float bb;
    if (o < 36) { wrow = loc_w + (size_t)o * 512; bb = loc_b[o]; }
    else { int a = o - 36; wrow = score_w + (size_t)(2 * a + 1) * 512; bb = score_b[2 * a + 1]; }
    float s = 0.f;
#pragma unroll 4
    for (int c = lane; c < 512; c += 32) s = fmaf(wrow[c], sh[c], s);
#pragma unroll
    for (int off = 16; off; off >>= 1) s += __shfl_down_sync(0xffffffffu, s, off);
    if (lane == 0) sums[o] = s + bb;
  }
  __syncthreads();

  if (tid < 9) {
    const int a = tid;
    float dy = sums[a * 4 + 0], dx = sums[a * 4 + 1];
    float dh = sums[a * 4 + 2], dw = sums[a * 4 + 3];
    float fg = sums[36 + a];
    int h = p / IW, w = p % IW;
    float sy = (float)h * 16.f, sx = (float)w * 16.f;
    float ay0 = __fadd_rn(sy, c_ab[a][0]);
    float ax0 = __fadd_rn(sx, c_ab[a][1]);
    float ay1 = __fadd_rn(sy, c_ab[a][2]);
    float ax1 = __fadd_rn(sx, c_ab[a][3]);
    float ah = __fadd_rn(ay1, -ay0);
    float aw = __fadd_rn(ax1, -ax0);
    float acy = __fadd_rn(ay0, __fmul_rn(0.5f, ah));
    float acx = __fadd_rn(ax0, __fmul_rn(0.5f, aw));
    float cy = __fadd_rn(__fmul_rn(dy, ah), acy);
    float cx = __fadd_rn(__fmul_rn(dx, aw), acx);
    float bh = __fmul_rn(expf(dh), ah);
    float bw = __fmul_rn(expf(dw), aw);
    float y1 = fminf(fmaxf(__fadd_rn(cy, -__fmul_rn(0.5f, bh)), 0.f), 608.f);
    float x1 = fminf(fmaxf(__fadd_rn(cx, -__fmul_rn(0.5f, bw)), 0.f), 800.f);
    float y2 = fminf(fmaxf(__fadd_rn(cy,  __fmul_rn(0.5f, bh)), 0.f), 608.f);
    float x2 = fminf(fmaxf(__fadd_rn(cx,  __fmul_rn(0.5f, bw)), 0.f), 800.f);
    bool valid = (__fadd_rn(y2, -y1) >= 16.f) && (__fadd_rn(x2, -x1) >= 16.f);
    float sc = valid ? fg : -__int_as_float(0x7f800000);

    int i = p * 9 + a;
    g_box[i * 4 + 0] = y1; g_box[i * 4 + 1] = x1;
    g_box[i * 4 + 2] = y2; g_box[i * 4 + 3] = x2;
    g_keys[i] = ((ull)f2key(sc) << 32) | (ull)(~(unsigned)i);
  }
}

// ---------------- fused bitonic sort (8 persistent blocks) --------------
__device__ __forceinline__ void grid_sync(unsigned& target) {
  __syncthreads();
  target += 8;
  if (threadIdx.x == 0) {
    __threadfence();
    atomicAdd(&g_bar, 1u);
    while (atomicAdd(&g_bar, 0u) < target) {}
    __threadfence();
  }
  __syncthreads();
}

__global__ __launch_bounds__(1024) void fused_sort() {
  __shared__ ull s[4096];
  const int base = blockIdx.x * 4096;
  const int t = threadIdx.x;
  unsigned bar_t = 0;

  // load + zero-pad beyond NANCH
#pragma unroll
  for (int m = 0; m < 4; ++m) {
    int l = t + m * 1024, e = base + l;
    s[l] = (e < NANCH) ? g_keys[e] : 0ull;
  }
  __syncthreads();

  // local sort k=2..4096 (R2-proven mapping + barriers)
  for (int k = 2; k <= 4096; k <<= 1) {
    for (int j = k >> 1; j > 0; j >>= 1) {
#pragma unroll
      for (int m = 0; m < 2; ++m) {
        int tt = t + m * 1024;
        int i = ((tt & ~(j - 1)) << 1) | (tt & (j - 1));
        int ix = i | j;
        bool desc = (((base + i) & k) == 0);
        ull a = s[i], b = s[ix];
        if (desc ? (a < b) : (a > b)) { s[i] = b; s[ix] = a; }
      }
      __syncthreads();
    }
  }

#define STORE_TO(buf) do {                                   \
    _Pragma("unroll")                                        \
    for (int m = 0; m < 4; ++m)                              \
      (buf)[base + t + m * 1024] = s[t + m * 1024];          \
  } while (0)

#define COMBINE(buf, K, J) do {                              \
    bool lower = ((base & (J)) == 0);                        \
    bool descC = ((base & (K)) == 0);                        \
    bool takeMax = (lower == descC);                         \
    _Pragma("unroll")                                        \
    for (int m = 0; m < 4; ++m) {                            \
      int l = t + m * 1024;                                  \
      ull v = __ldcg(&(buf)[(base + l) ^ (J)]);              \
      ull mv = s[l];                                         \
      s[l] = takeMax ? (mv > v ? mv : v) : (mv < v ? mv : v);\
    }                                                        \
    __syncthreads();                                         \
  } while (0)

#define TAIL(K) do {                                         \
    bool descT = ((base & (K)) == 0);                        \
    for (int j = 2048; j > 0; j >>= 1) {                     \
      _Pragma("unroll")                                      \
      for (int m = 0; m < 2; ++m) {                          \
        int tt = t + m * 1024;                               \
        int i = ((tt & ~(j - 1)) << 1) | (tt & (j - 1));     \
        int ix = i | j;                                      \
        ull a = s[i], b = s[ix];                             \
        if (descT ? (a < b) : (a > b)) { s[i] = b; s[ix] = a; } \
      }                                                      \
      __syncthreads();                                       \
    }                                                        \
  } while (0)

  STORE_TO(g_keys);  grid_sync(bar_t);
  COMBINE(g_keys, 8192, 4096);  TAIL(8192);

  STORE_TO(g_keys2); grid_sync(bar_t);
  COMBINE(g_keys2, 16384, 8192);

  STORE_TO(g_keys);  grid_sync(bar_t);
  COMBINE(g_keys, 16384, 4096);  TAIL(16384);

  STORE_TO(g_keys2); grid_sync(bar_t);
  COMBINE(g_keys2, 32768, 16384);

  STORE_TO(g_keys);  grid_sync(bar_t);
  COMBINE(g_keys, 32768, 8192);

  STORE_TO(g_keys2); grid_sync(bar_t);
  COMBINE(g_keys2, 32768, 4096);  TAIL(32768);   // base&32768==0 -> descending

  // epilogue: gather boxes + validity ballots (only e < 6144 matters)
  if (base < 6144) {
#pragma unroll
    for (int m = 0; m < 4; ++m) {
      int l = t + m * 1024, e = base + l;
      if (e < 6144) {                       // warp-uniform (1024-aligned spans)
        ull key = s[l];
        bool valid = (e < PRE_N) && ((unsigned)(key >> 32) > 0x007FFFFFu);
        unsigned bal = __ballot_sync(0xffffffffu, valid);
        if ((t & 31) == 0) ((unsigned*)g_validw)[e >> 5] = bal;
        if (e < PRE_N) {
          unsigned idx = ~(unsigned)(key & 0xffffffffull);
          float4 b = make_float4(0.f, 0.f, 0.f, 0.f);
          if (idx < NANCH) b = ((const float4*)g_box)[idx];
          ((float4*)g_tb)[e] = b;
        }
      }
    }
  }
#undef STORE_TO
#undef COMBINE
#undef TAIL
}

// ---------------- NMS suppression-mask matrix (upper triangle) ----------
__global__ __launch_bounds__(64) void nms_mask() {
  const int cb = blockIdx.x;
  const int rb = blockIdx.y;
  if (cb < rb) return;
  const int tid = threadIdx.x;
  __shared__ float4 colb[64];
  __shared__ float cola[64];
  int j0 = cb * 64;
  int jj = j0 + tid;
  float4 b = (jj < PRE_N) ? ((const float4*)g_tb)[jj] : make_float4(0.f,0.f,0.f,0.f);
  colb[tid] = b;
  cola[tid] = __fmul_rn(__fadd_rn(b.z, -b.x), __fadd_rn(b.w, -b.y));
  __syncthreads();
  int i = rb * 64 + tid;
  if (i >= PRE_N) return;
  float4 r = ((const float4*)g_tb)[i];
  float ra = __fmul_rn(__fadd_rn(r.z, -r.x), __fadd_rn(r.w, -r.y));
  ull bits = 0ull;
  int jmax = min(64, PRE_N - j0);
  for (int q = 0; q < jmax; ++q) {
    int j = j0 + q;
    if (j <= i) continue;
    float4 c = colb[q];
    float ty1 = fmaxf(r.x, c.x);
    float tx1 = fmaxf(r.y, c.y);
    float ty2 = fminf(r.z, c.z);
    float tx2 = fminf(r.w, c.w);
    float ihh = fmaxf(__fadd_rn(ty2, -ty1), 0.f);
    float iww = fmaxf(__fadd_rn(tx2, -tx1), 0.f);
    float inter = __fmul_rn(ihh, iww);
    float uni = fmaxf(__fadd_rn(__fadd_rn(ra, cola[q]), -inter), 1e-9f);
    float rhs = 0.7f * uni;
    bool sup;
    if (inter > rhs * 1.00001f)       sup = true;
    else if (inter < rhs * 0.99999f)  sup = false;
    else sup = (__fdiv_rn(inter, uni) > 0.7f);
    if (sup) bits |= (1ull << q);
  }
  g_mask[(size_t)i * MASKW + cb] = bits;
}

// ---- NMS scan: ffs bit-walk + parallel row fold, early stop @300 -------
__global__ __launch_bounds__(256) void nms_scan(float* __restrict__ out) {
  __shared__ ull remv[MASKW];
  __shared__ int keptIdx[POST_N];
  __shared__ int wordKept[64];
  __shared__ int s_nk, s_nwk;
  const int tid = threadIdx.x;
  if (tid < MASKW) remv[tid] = 0ull;
  if (tid == 0) s_nk = 0;
  for (int i = tid; i < POST_N * 4; i += 256) out[i] = 0.f;
  __syncthreads();

  for (int w = 0; w < MASKW; ++w) {
    if (tid < 32) {
      ull vw = g_validw[w];
      ull alive = vw & ~remv[w];
      int base = w * 64;
      ull mA = ((alive >> tid) & 1ull) ? g_mask[(size_t)(base + tid) * MASKW + w] : 0ull;
      ull mB = ((alive >> (tid + 32)) & 1ull) ? g_mask[(size_t)(base + tid + 32) * MASKW + w] : 0ull;
      int nk = s_nk, nwk = 0;
      while (alive && nk < POST_N) {
        int q = __ffsll((long long)alive) - 1;
        ull mq = (q < 32) ? __shfl_sync(0xffffffffu, mA, q)
                          : __shfl_sync(0xffffffffu, mB, q - 32);
        if (tid == 0) { keptIdx[nk] = base + q; wordKept[nwk] = base + q; }
        ++nk; ++nwk;
        alive &= ~((1ull << q) | mq);
      }
      if (tid == 0) { s_nk = nk; s_nwk = nwk; }
    }
    __syncthreads();
    int total = s_nwk * MASKW;
    for (int e = tid; e < total; e += 256) {
      int r = e / MASKW, wd = e - r * MASKW;
      ull m = g_mask[(size_t)wordKept[r] * MASKW + wd];
      if (m) atomicOr(&remv[wd], m);
    }
    __syncthreads();
    if (s_nk >= POST_N) break;
  }

  __syncthreads();
  for (int r = tid; r < s_nk; r += 256)
    ((float4*)out)[r] = ((const float4*)g_tb)[keptIdx[r]];
}

// ---------------- launcher ----------------
extern "C" void kernel_launch(void* const* d_in, const int* in_sizes, int n_in,
                              void* d_out, int out_size) {
  const float* x        = (const float*)d_in[0];
  const float* conv1_w  = (const float*)d_in[1];
  const float* conv1_b  = (const float*)d_in[2];
  const float* loc_w    = (const float*)d_in[3];
  const float* loc_b    = (const float*)d_in[4];
  const float* score_w  = (const float*)d_in[5];
  const float* score_b  = (const float*)d_in[6];
  float* out = (float*)d_out;

  dim3 cgrid(7, 5, 8);
  conv3x3_relu<<<cgrid, 256>>>(x, conv1_w, conv1_b);
  rpn_head<<<HWPIX, 256>>>(loc_w, loc_b, score_w, score_b);
  fused_sort<<<8, 1024>>>();
  nms_mask<<<dim3(MASKW, MASKW), 64>>>();
  nms_scan<<<1, 256>>>(out);
}

// round 7
// speedup vs baseline: 1.0973x; 1.0216x over previous
#include <cuda_runtime.h>

#define C_IN   512
#define IH     38
#define IW     50
#define HWPIX  1900
#define NANCH  17100
#define NSORT  32768
#define PRE_N  6000
#define POST_N 300
#define MASKW  94        // ceil(6000/64)

typedef unsigned long long ull;

// ---------------- device scratch (static, no allocation) ----------------
__device__ float    g_h1T[HWPIX * 512];                // conv output, [pixel][k]
__device__ float    g_box[NANCH * 4];                  // decoded clipped boxes
__device__ ull      g_keys[NSORT];                     // ping buffer
__device__ ull      g_keys2[NSORT];                    // pong buffer
__device__ float    g_tb[PRE_N * 4];                   // top-6000 boxes (sorted)
__device__ ull      g_mask[(size_t)PRE_N * MASKW];     // lower tri never written
__device__ ull      g_validw[96];                      // validity bits of top-6000
__device__ unsigned g_bar;                             // grid spin barrier

__constant__ float c_ab[9][4] = {
  {-37.254833f,  -82.50967f,   53.254833f,  98.50967f},
  {-82.50967f,  -173.01933f,   98.50967f,  189.01933f},
  {-173.01933f, -354.03867f,  189.01933f,  370.03867f},
  {-56.0f,       -56.0f,        72.0f,       72.0f},
  {-120.0f,     -120.0f,       136.0f,      136.0f},
  {-248.0f,     -248.0f,       264.0f,      264.0f},
  {-82.50967f,   -37.254833f,  98.50967f,   53.254833f},
  {-173.01933f,  -82.50967f,  189.01933f,   98.50967f},
  {-354.03867f, -173.01933f,  370.03867f,  189.01933f}};

// ---------------- f32x2 helpers ----------------
__device__ __forceinline__ ull dup2(float v) {
  ull r; asm("mov.b64 %0, {%1, %1};" : "=l"(r) : "f"(v)); return r;
}
__device__ __forceinline__ void fma2(ull& d, ull a, ull b) {
  asm("fma.rn.f32x2 %0, %1, %2, %0;" : "+l"(d) : "l"(a), "l"(b));
}
__device__ __forceinline__ float2 unpk(ull v) {
  float2 f; asm("mov.b64 {%0, %1}, %2;" : "=f"(f.x), "=f"(f.y) : "l"(v)); return f;
}

// ---------------- 3x3 conv + bias + relu -> g_h1T[p][k] ----------------
__global__ __launch_bounds__(256) void conv3x3_relu(
    const float* __restrict__ x, const float* __restrict__ wgt,
    const float* __restrict__ bias) {
  const int wt = blockIdx.x;            // 0..6
  const int ht = blockIdx.y;            // 0..4
  const int kt = blockIdx.z;            // 0..7
  const int h0 = ht * 8, w0 = wt * 8;
  const int tid = threadIdx.x;
  const int ty  = tid >> 4;             // 0..15 (k groups of 4)
  const int txp = tid & 15;
  const int hh  = txp >> 1;             // 0..7
  const int wq  = txp & 1;              // 0..1 (w groups of 4)

  __shared__ float sW[72 * 66];                     // [crs][k], stride 66
  __shared__ __align__(16) float sX[8][10][12];     // [c][row][col]

  ull a00 = 0, a01 = 0, a02 = 0, a03 = 0;
  ull a10 = 0, a11 = 0, a12 = 0, a13 = 0;

  const int k0g = kt * 64;

  for (int c0 = 0; c0 < C_IN; c0 += 8) {
    __syncthreads();
#pragma unroll
    for (int l = 0; l < 18; ++l) {
      int idx = tid + l * 256;          // = k*72 + crs
      int k = idx / 72, crs = idx % 72;
      sW[crs * 66 + k] = wgt[(size_t)(k0g + k) * 4608 + (size_t)c0 * 9 + crs];
    }
    for (int idx = tid; idx < 800; idx += 256) {
      int c = idx / 100, rem = idx % 100;
      int row = rem / 10, col = rem % 10;
      int gh = h0 - 1 + row, gw = w0 - 1 + col;
      float v = 0.f;
      if (gh >= 0 && gh < IH && gw >= 0 && gw < IW)
        v = x[(size_t)(c0 + c) * HWPIX + gh * IW + gw];
      sX[c][row][col] = v;
    }
    __syncthreads();

#pragma unroll 2
    for (int c = 0; c < 8; ++c) {
#pragma unroll
      for (int r = 0; r < 3; ++r) {
        const float* xp = &sX[c][hh + r][wq * 4];
        float4 xa = *(const float4*)xp;
        float2 xb = *(const float2*)(xp + 4);
        ull xd[6] = {dup2(xa.x), dup2(xa.y), dup2(xa.z),
                     dup2(xa.w), dup2(xb.x), dup2(xb.y)};
#pragma unroll
        for (int s = 0; s < 3; ++s) {
          int wi = (c * 9 + r * 3 + s) * 66 + ty * 4;
          ull w01 = *(const ull*)&sW[wi];
          ull w23 = *(const ull*)&sW[wi + 2];
          fma2(a00, w01, xd[s + 0]);
          fma2(a01, w01, xd[s + 1]);
          fma2(a02, w01, xd[s + 2]);
          fma2(a03, w01, xd[s + 3]);
          fma2(a10, w23, xd[s + 0]);
          fma2(a11, w23, xd[s + 1]);
          fma2(a12, w23, xd[s + 2]);
          fma2(a13, w23, xd[s + 3]);
        }
      }
    }
  }

  const int h = h0 + hh;
  if (h < IH) {
    float b0 = bias[k0g + ty * 4 + 0];
    float b1 = bias[k0g + ty * 4 + 1];
    float b2 = bias[k0g + ty * 4 + 2];
    float b3 = bias[k0g + ty * 4 + 3];
    float2 p0[4] = {unpk(a00), unpk(a01), unpk(a02), unpk(a03)};
    float2 p1[4] = {unpk(a10), unpk(a11), unpk(a12), unpk(a13)};
#pragma unroll
    for (int j = 0; j < 4; ++j) {
      int ww = w0 + wq * 4 + j;
      if (ww < IW) {
        int p = h * IW + ww;
        float4 o;
        o.x = fmaxf(p0[j].x + b0, 0.f);
        o.y = fmaxf(p0[j].y + b1, 0.f);
        o.z = fmaxf(p1[j].x + b2, 0.f);
        o.w = fmaxf(p1[j].y + b3, 0.f);
        *(float4*)(&g_h1T[(size_t)p * 512 + k0g + ty * 4]) = o;
      }
    }
  }
}

// ------- 1x1 heads (4 pixels/block) + anchor decode + key build ---------
__device__ __forceinline__ unsigned f2key(float f) {
  unsigned u = __float_as_uint(f);
  return (u & 0x80000000u) ? ~u : (u | 0x80000000u);
}

__global__ __launch_bounds__(256) void rpn_head(
    const float* __restrict__ loc_w, const float* __restrict__ loc_b,
    const float* __restrict__ score_w, const float* __restrict__ score_b) {
  const int pb = blockIdx.x;            // 0..474 (4 pixels each; 1900 = 475*4)
  const int tid = threadIdx.x;
  if (pb == 0 && tid == 0) g_bar = 0u;  // reset grid barrier for fused_sort
  __shared__ float sh[4][512];
  __shared__ float sums[4][48];         // per-pixel: 36 loc + 9 fg
  const int p0 = pb * 4;

  // load 4 pixel feature vectors (1024 float2, 256 threads -> 4 each)
#pragma unroll
  for (int m = 0; m < 4; ++m) {
    int idx = tid + m * 256;            // 0..1023
    int px = idx >> 8, off = idx & 255;
    ((float2*)sh[px])[off] =
        ((const float2*)(g_h1T + (size_t)(p0 + px) * 512))[off];
  }
  __syncthreads();

  const int wid = tid >> 5, lane = tid & 31;
  for (int o = wid; o < 45; o += 8) {
    const float* wrow;
    float bb;
    if (o < 36) { wrow = loc_w + (size_t)o * 512; bb = loc_b[o]; }
    else { int a = o - 36; wrow = score_w + (size_t)(2 * a + 1) * 512; bb = score_b[2 * a + 1]; }
    float s0 = 0.f, s1 = 0.f, s2 = 0.f, s3 = 0.f;
#pragma unroll 4
    for (int c = lane; c < 512; c += 32) {
      float wv = wrow[c];
      s0 = fmaf(wv, sh[0][c], s0);
      s1 = fmaf(wv, sh[1][c], s1);
      s2 = fmaf(wv, sh[2][c], s2);
      s3 = fmaf(wv, sh[3][c], s3);
    }
#pragma unroll
    for (int off = 16; off; off >>= 1) {
      s0 += __shfl_down_sync(0xffffffffu, s0, off);
      s1 += __shfl_down_sync(0xffffffffu, s1, off);
      s2 += __shfl_down_sync(0xffffffffu, s2, off);
      s3 += __shfl_down_sync(0xffffffffu, s3, off);
    }
    if (lane == 0) {
      sums[0][o] = s0 + bb; sums[1][o] = s1 + bb;
      sums[2][o] = s2 + bb; sums[3][o] = s3 + bb;
    }
  }
  __syncthreads();

  if (tid < 36) {
    const int px = tid / 9, a = tid % 9;
    const int p = p0 + px;
    float dy = sums[px][a * 4 + 0], dx = sums[px][a * 4 + 1];
    float dh = sums[px][a * 4 + 2], dw = sums[px][a * 4 + 3];
    float fg = sums[px][36 + a];
    int h = p / IW, w = p % IW;
    float sy = (float)h * 16.f, sx = (float)w * 16.f;
    float ay0 = __fadd_rn(sy, c_ab[a][0]);
    float ax0 = __fadd_rn(sx, c_ab[a][1]);
    float ay1 = __fadd_rn(sy, c_ab[a][2]);
    float ax1 = __fadd_rn(sx, c_ab[a][3]);
    float ah = __fadd_rn(ay1, -ay0);
    float aw = __fadd_rn(ax1, -ax0);
    float acy = __fadd_rn(ay0, __fmul_rn(0.5f, ah));
    float acx = __fadd_rn(ax0, __fmul_rn(0.5f, aw));
    float cy = __fadd_rn(__fmul_rn(dy, ah), acy);
    float cx = __fadd_rn(__fmul_rn(dx, aw), acx);
    float bh = __fmul_rn(expf(dh), ah);
    float bw = __fmul_rn(expf(dw), aw);
    float y1 = fminf(fmaxf(__fadd_rn(cy, -__fmul_rn(0.5f, bh)), 0.f), 608.f);
    float x1 = fminf(fmaxf(__fadd_rn(cx, -__fmul_rn(0.5f, bw)), 0.f), 800.f);
    float y2 = fminf(fmaxf(__fadd_rn(cy,  __fmul_rn(0.5f, bh)), 0.f), 608.f);
    float x2 = fminf(fmaxf(__fadd_rn(cx,  __fmul_rn(0.5f, bw)), 0.f), 800.f);
    bool valid = (__fadd_rn(y2, -y1) >= 16.f) && (__fadd_rn(x2, -x1) >= 16.f);
    float sc = valid ? fg : -__int_as_float(0x7f800000);

    int i = p * 9 + a;
    g_box[i * 4 + 0] = y1; g_box[i * 4 + 1] = x1;
    g_box[i * 4 + 2] = y2; g_box[i * 4 + 3] = x2;
    g_keys[i] = ((ull)f2key(sc) << 32) | (ull)(~(unsigned)i);
  }
}

// ---------------- fused bitonic sort (8 persistent blocks) --------------
__device__ __forceinline__ void grid_sync(unsigned& target) {
  __syncthreads();
  target += 8;
  if (threadIdx.x == 0) {
    __threadfence();
    atomicAdd(&g_bar, 1u);
    while (atomicAdd(&g_bar, 0u) < target) {}
    __threadfence();
  }
  __syncthreads();
}

__global__ __launch_bounds__(1024) void fused_sort() {
  __shared__ ull s[4096];
  const int base = blockIdx.x * 4096;
  const int t = threadIdx.x;
  unsigned bar_t = 0;

#pragma unroll
  for (int m = 0; m < 4; ++m) {
    int l = t + m * 1024, e = base + l;
    s[l] = (e < NANCH) ? g_keys[e] : 0ull;
  }
  __syncthreads();

  for (int k = 2; k <= 4096; k <<= 1) {
    for (int j = k >> 1; j > 0; j >>= 1) {
#pragma unroll
      for (int m = 0; m < 2; ++m) {
        int tt = t + m * 1024;
        int i = ((tt & ~(j - 1)) << 1) | (tt & (j - 1));
        int ix = i | j;
        bool desc = (((base + i) & k) == 0);
        ull a = s[i], b = s[ix];
        if (desc ? (a < b) : (a > b)) { s[i] = b; s[ix] = a; }
      }
      __syncthreads();
    }
  }

#define STORE_TO(buf) do {                                   \
    _Pragma("unroll")                                        \
    for (int m = 0; m < 4; ++m)                              \
      (buf)[base + t + m * 1024] = s[t + m * 1024];          \
  } while (0)

#define COMBINE(buf, K, J) do {                              \
    bool lower = ((base & (J)) == 0);                        \
    bool descC = ((base & (K)) == 0);                        \
    bool takeMax = (lower == descC);                         \
    _Pragma("unroll")                                        \
    for (int m = 0; m < 4; ++m) {                            \
      int l = t + m * 1024;                                  \
      ull v = __ldcg(&(buf)[(base + l) ^ (J)]);              \
      ull mv = s[l];                                         \
      s[l] = takeMax ? (mv > v ? mv : v) : (mv < v ? mv : v);\
    }                                                        \
    __syncthreads();                                         \
  } while (0)

#define TAIL(K) do {                                         \
    bool descT = ((base & (K)) == 0);                        \
    for (int j = 2048; j > 0; j >>= 1) {                     \
      _Pragma("unroll")                                      \
      for (int m = 0; m < 2; ++m) {                          \
        int tt = t + m * 1024;                               \
        int i = ((tt & ~(j - 1)) << 1) | (tt & (j - 1));     \
        int ix = i | j;                                      \
        ull a = s[i], b = s[ix];                             \
        if (descT ? (a < b) : (a > b)) { s[i] = b; s[ix] = a; } \
      }                                                      \
      __syncthreads();                                       \
    }                                                        \
  } while (0)

  STORE_TO(g_keys);  grid_sync(bar_t);
  COMBINE(g_keys, 8192, 4096);  TAIL(8192);

  STORE_TO(g_keys2); grid_sync(bar_t);
  COMBINE(g_keys2, 16384, 8192);

  STORE_TO(g_keys);  grid_sync(bar_t);
  COMBINE(g_keys, 16384, 4096);  TAIL(16384);

  STORE_TO(g_keys2); grid_sync(bar_t);
  COMBINE(g_keys2, 32768, 16384);

  STORE_TO(g_keys);  grid_sync(bar_t);
  COMBINE(g_keys, 32768, 8192);

  STORE_TO(g_keys2); grid_sync(bar_t);
  COMBINE(g_keys2, 32768, 4096);  TAIL(32768);

  // epilogue: gather boxes + validity ballots (only e < 6144 matters)
  if (base < 6144) {
#pragma unroll
    for (int m = 0; m < 4; ++m) {
      int l = t + m * 1024, e = base + l;
      if (e < 6144) {
        ull key = s[l];
        bool valid = (e < PRE_N) && ((unsigned)(key >> 32) > 0x007FFFFFu);
        unsigned bal = __ballot_sync(0xffffffffu, valid);
        if ((t & 31) == 0) ((unsigned*)g_validw)[e >> 5] = bal;
        if (e < PRE_N) {
          unsigned idx = ~(unsigned)(key & 0xffffffffull);
          float4 b = make_float4(0.f, 0.f, 0.f, 0.f);
          if (idx < NANCH) b = ((const float4*)g_box)[idx];
          ((float4*)g_tb)[e] = b;
        }
      }
    }
  }
#undef STORE_TO
#undef COMBINE
#undef TAIL
}

// ------- NMS mask: 128-row x 64-col tiles, fully unrolled inner ---------
__global__ __launch_bounds__(128) void nms_mask() {
  const int cb = blockIdx.x;      // 0..93 (col block)
  const int rb = blockIdx.y;      // 0..46 (row block of 128)
  if (cb < 2 * rb) return;        // whole tile strictly lower-triangular
  const int tid = threadIdx.x;
  __shared__ float4 colb[64];
  __shared__ float cola[64];
  const int j0 = cb * 64;
  if (tid < 64) {
    int jj = j0 + tid;
    float4 b = (jj < PRE_N) ? ((const float4*)g_tb)[jj]
                            : make_float4(0.f, 0.f, 0.f, 0.f);
    colb[tid] = b;
    cola[tid] = __fmul_rn(__fadd_rn(b.z, -b.x), __fadd_rn(b.w, -b.y));
  }
  __syncthreads();
  const int i = rb * 128 + tid;
  if (i >= PRE_N) return;
  if (i >= j0 + 64) return;       // all cols <= i: lower-tri word stays zero
  float4 r = ((const float4*)g_tb)[i];
  float ra = __fmul_rn(__fadd_rn(r.z, -r.x), __fadd_rn(r.w, -r.y));
  ull bits = 0ull;
#pragma unroll
  for (int q = 0; q < 64; ++q) {
    float4 c = colb[q];
    float ty1 = fmaxf(r.x, c.x);
    float tx1 = fmaxf(r.y, c.y);
    float ty2 = fminf(r.z, c.z);
    float tx2 = fminf(r.w, c.w);
    float ihh = fmaxf(__fadd_rn(ty2, -ty1), 0.f);
    float iww = fmaxf(__fadd_rn(tx2, -tx1), 0.f);
    float inter = __fmul_rn(ihh, iww);
    float uni = fmaxf(__fadd_rn(__fadd_rn(ra, cola[q]), -inter), 1e-9f);
    float d = __fmaf_rn(-0.7f, uni, inter);
    bool sup;
    if (fabsf(d) < 3e-5f * uni)                      // rare boundary band
      sup = (__fdiv_rn(inter, uni) > 0.7f);          // exact (matches reference)
    else
      sup = d > 0.f;
    if (sup) bits |= (1ull << q);
  }
  if (j0 <= i) {                   // diagonal tile: keep only cols > i
    int dq = i - j0;               // 0..63
    bits = (dq >= 63) ? 0ull : (bits & (~0ull << (dq + 1)));
  }
  g_mask[(size_t)i * MASKW + cb] = bits;
}

// ---- NMS scan: ffs bit-walk + parallel row fold, early stop @300 -------
__global__ __launch_bounds__(256) void nms_scan(float* __restrict__ out) {
  __shared__ ull remv[MASKW];
  __shared__ int keptIdx[POST_N];
  __shared__ int wordKept[64];
  __shared__ int s_nk, s_nwk;
  const int tid = threadIdx.x;
  if (tid < MASKW) remv[tid] = 0ull;
  if (tid == 0) s_nk = 0;
  for (int i = tid; i < POST_N * 4; i += 256) out[i] = 0.f;
  __syncthreads();

  for (int w = 0; w < MASKW; ++w) {
    if (tid < 32) {
      ull vw = g_validw[w];
      ull alive = vw & ~remv[w];
      int base = w * 64;
      ull mA = ((alive >> tid) & 1ull) ? g_mask[(size_t)(base + tid) * MASKW + w] : 0ull;
      ull mB = ((alive >> (tid + 32)) & 1ull) ? g_mask[(size_t)(base + tid + 32) * MASKW + w] : 0ull;
      int nk = s_nk, nwk = 0;
      while (alive && nk < POST_N) {
        int q = __ffsll((long long)alive) - 1;
        ull mq = (q < 32) ? __shfl_sync(0xffffffffu, mA, q)
                          : __shfl_sync(0xffffffffu, mB, q - 32);
        if (tid == 0) { keptIdx[nk] = base + q; wordKept[nwk] = base + q; }
        ++nk; ++nwk;
        alive &= ~((1ull << q) | mq);
      }
      if (tid == 0) { s_nk = nk; s_nwk = nwk; }
    }
    __syncthreads();
    int total = s_nwk * MASKW;
    for (int e = tid; e < total; e += 256) {
      int r = e / MASKW, wd = e - r * MASKW;
      ull m = g_mask[(size_t)wordKept[r] * MASKW + wd];
      if (m) atomicOr(&remv[wd], m);
    }
    __syncthreads();
    if (s_nk >= POST_N) break;
  }

  __syncthreads();
  for (int r = tid; r < s_nk; r += 256)
    ((float4*)out)[r] = ((const float4*)g_tb)[keptIdx[r]];
}

// ---------------- launcher ----------------
extern "C" void kernel_launch(void* const* d_in, const int* in_sizes, int n_in,
                              void* d_out, int out_size) {
  const float* x        = (const float*)d_in[0];
  const float* conv1_w  = (const float*)d_in[1];
  const float* conv1_b  = (const float*)d_in[2];
  const float* loc_w    = (const float*)d_in[3];
  const float* loc_b    = (const float*)d_in[4];
  const float* score_w  = (const float*)d_in[5];
  const float* score_b  = (const float*)d_in[6];
  float* out = (float*)d_out;

  dim3 cgrid(7, 5, 8);
  conv3x3_relu<<<cgrid, 256>>>(x, conv1_w, conv1_b);
  rpn_head<<<475, 256>>>(loc_w, loc_b, score_w, score_b);
  fused_sort<<<8, 1024>>>();
  nms_mask<<<dim3(94, 47), 128>>>();
  nms_scan<<<1, 256>>>(out);
}

// round 8
// speedup vs baseline: 1.2032x; 1.0966x over previous
#include <cuda_runtime.h>

#define C_IN   512
#define IH     38
#define IW     50
#define HWPIX  1900
#define NANCH  17100
#define NSORT  32768
#define PRE_N  6000
#define POST_N 300
#define MASKW  94        // ceil(6000/64)

typedef unsigned long long ull;

// ---------------- device scratch (static, no allocation) ----------------
__device__ float    g_h1T[HWPIX * 512];                // conv output, [pixel][k]
__device__ float    g_box[NANCH * 4];                  // decoded clipped boxes
__device__ ull      g_keys[NSORT];                     // ping buffer
__device__ ull      g_keys2[NSORT];                    // pong buffer
__device__ float    g_tb[PRE_N * 4];                   // top-6000 boxes (sorted)
__device__ ull      g_mask[(size_t)PRE_N * MASKW];     // lower tri never written
__device__ ull      g_validw[96];                      // validity bits of top-6000
__device__ unsigned g_bar;                             // grid spin barrier

__constant__ float c_ab[9][4] = {
  {-37.254833f,  -82.50967f,   53.254833f,  98.50967f},
  {-82.50967f,  -173.01933f,   98.50967f,  189.01933f},
  {-173.01933f, -354.03867f,  189.01933f,  370.03867f},
  {-56.0f,       -56.0f,        72.0f,       72.0f},
  {-120.0f,     -120.0f,       136.0f,      136.0f},
  {-248.0f,     -248.0f,       264.0f,      264.0f},
  {-82.50967f,   -37.254833f,  98.50967f,   53.254833f},
  {-173.01933f,  -82.50967f,  189.01933f,   98.50967f},
  {-354.03867f, -173.01933f,  370.03867f,  189.01933f}};

// ---------------- f32x2 helpers ----------------
__device__ __forceinline__ ull dup2(float v) {
  ull r; asm("mov.b64 %0, {%1, %1};" : "=l"(r) : "f"(v)); return r;
}
__device__ __forceinline__ void fma2(ull& d, ull a, ull b) {
  asm("fma.rn.f32x2 %0, %1, %2, %0;" : "+l"(d) : "l"(a), "l"(b));
}
__device__ __forceinline__ float2 unpk(ull v) {
  float2 f; asm("mov.b64 {%0, %1}, %2;" : "=f"(f.x), "=f"(f.y) : "l"(v)); return f;
}

// ------- 3x3 conv + bias + relu, double-buffered + reg-staged prefetch --
__global__ __launch_bounds__(256) void conv3x3_relu(
    const float* __restrict__ x, const float* __restrict__ wgt,
    const float* __restrict__ bias) {
  const int wt = blockIdx.x;            // 0..6
  const int ht = blockIdx.y;            // 0..4
  const int kt = blockIdx.z;            // 0..7
  const int h0 = ht * 8, w0 = wt * 8;
  const int tid = threadIdx.x;
  const int ty  = tid >> 4;             // 0..15 (k groups of 4)
  const int txp = tid & 15;
  const int hh  = txp >> 1;             // 0..7
  const int wq  = txp & 1;              // 0..1 (w groups of 4)

  __shared__ float sW[2][72 * 66];                  // [buf][crs*66+k]
  __shared__ __align__(16) float sX[2][8][10][12];  // [buf][c][row][col]

  ull a00 = 0, a01 = 0, a02 = 0, a03 = 0;
  ull a10 = 0, a11 = 0, a12 = 0, a13 = 0;

  const int k0g = kt * 64;

  // per-thread static load indices
  int wk[18], wcrs[18];
#pragma unroll
  for (int l = 0; l < 18; ++l) {
    int idx = tid + l * 256;            // = k*72 + crs
    wk[l] = idx / 72; wcrs[l] = idx % 72;
  }
  int xc[4], xrow[4], xcol[4];
  bool xon[4];
#pragma unroll
  for (int m = 0; m < 4; ++m) {
    int idx = tid + m * 256;
    xon[m] = idx < 800;
    int c = idx / 100, rem = idx % 100;
    xc[m] = c; xrow[m] = rem / 10; xcol[m] = rem % 10;
  }

  // prologue: fill buffer 0 for c0=0
  {
#pragma unroll
    for (int l = 0; l < 18; ++l)
      sW[0][wcrs[l] * 66 + wk[l]] =
          wgt[(size_t)(k0g + wk[l]) * 4608 + wcrs[l]];
#pragma unroll
    for (int m = 0; m < 4; ++m) {
      if (xon[m]) {
        int gh = h0 - 1 + xrow[m], gw = w0 - 1 + xcol[m];
        float v = 0.f;
        if (gh >= 0 && gh < IH && gw >= 0 && gw < IW)
          v = x[(size_t)xc[m] * HWPIX + gh * IW + gw];
        sX[0][xc[m]][xrow[m]][xcol[m]] = v;
      }
    }
  }
  __syncthreads();

  for (int c0 = 0; c0 < C_IN; c0 += 8) {
    const int cur = (c0 >> 3) & 1;
    const int nxt = cur ^ 1;
    const bool more = (c0 + 8) < C_IN;

    // ---- stage next iteration's data into registers (LDG issues early) --
    float wreg[18];
    float xreg[4];
    if (more) {
      const int c1 = c0 + 8;
#pragma unroll
      for (int l = 0; l < 18; ++l)
        wreg[l] = wgt[(size_t)(k0g + wk[l]) * 4608 + (size_t)c1 * 9 + wcrs[l]];
#pragma unroll
      for (int m = 0; m < 4; ++m) {
        float v = 0.f;
        if (xon[m]) {
          int gh = h0 - 1 + xrow[m], gw = w0 - 1 + xcol[m];
          if (gh >= 0 && gh < IH && gw >= 0 && gw < IW)
            v = x[(size_t)(c1 + xc[m]) * HWPIX + gh * IW + gw];
        }
        xreg[m] = v;
      }
    }

    // ---- compute from buf[cur] (identical math/order to previous rounds)
    const float* sWc = sW[cur];
#pragma unroll
    for (int c = 0; c < 8; ++c) {
#pragma unroll
      for (int r = 0; r < 3; ++r) {
        const float* xp = &sX[cur][c][hh + r][wq * 4];
        float4 xa = *(const float4*)xp;
        float2 xb = *(const float2*)(xp + 4);
        ull xd[6] = {dup2(xa.x), dup2(xa.y), dup2(xa.z),
                     dup2(xa.w), dup2(xb.x), dup2(xb.y)};
#pragma unroll
        for (int s = 0; s < 3; ++s) {
          int wi = (c * 9 + r * 3 + s) * 66 + ty * 4;
          ull w01 = *(const ull*)&sWc[wi];
          ull w23 = *(const ull*)&sWc[wi + 2];
          fma2(a00, w01, xd[s + 0]);
          fma2(a01, w01, xd[s + 1]);
          fma2(a02, w01, xd[s + 2]);
          fma2(a03, w01, xd[s + 3]);
          fma2(a10, w23, xd[s + 0]);
          fma2(a11, w23, xd[s + 1]);
          fma2(a12, w23, xd[s + 2]);
          fma2(a13, w23, xd[s + 3]);
        }
      }
    }

    // ---- drain staged registers into the other buffer, single sync -----
    if (more) {
#pragma unroll
      for (int l = 0; l < 18; ++l)
        sW[nxt][wcrs[l] * 66 + wk[l]] = wreg[l];
#pragma unroll
      for (int m = 0; m < 4; ++m)
        if (xon[m]) sX[nxt][xc[m]][xrow[m]][xcol[m]] = xreg[m];
    }
    __syncthreads();
  }

  const int h = h0 + hh;
  if (h < IH) {
    float b0 = bias[k0g + ty * 4 + 0];
    float b1 = bias[k0g + ty * 4 + 1];
    float b2 = bias[k0g + ty * 4 + 2];
    float b3 = bias[k0g + ty * 4 + 3];
    float2 p0[4] = {unpk(a00), unpk(a01), unpk(a02), unpk(a03)};
    float2 p1[4] = {unpk(a10), unpk(a11), unpk(a12), unpk(a13)};
#pragma unroll
    for (int j = 0; j < 4; ++j) {
      int ww = w0 + wq * 4 + j;
      if (ww < IW) {
        int p = h * IW + ww;
        float4 o;
        o.x = fmaxf(p0[j].x + b0, 0.f);
        o.y = fmaxf(p0[j].y + b1, 0.f);
        o.z = fmaxf(p1[j].x + b2, 0.f);
        o.w = fmaxf(p1[j].y + b3, 0.f);
        *(float4*)(&g_h1T[(size_t)p * 512 + k0g + ty * 4]) = o;
      }
    }
  }
}

// ------- 1x1 heads (4 pixels/block) + anchor decode + key build ---------
__device__ __forceinline__ unsigned f2key(float f) {
  unsigned u = __float_as_uint(f);
  return (u & 0x80000000u) ? ~u : (u | 0x80000000u);
}

__global__ __launch_bounds__(256) void rpn_head(
    const float* __restrict__ loc_w, const float* __restrict__ loc_b,
    const float* __restrict__ score_w, const float* __restrict__ score_b) {
  const int pb = blockIdx.x;            // 0..474 (4 pixels each)
  const int tid = threadIdx.x;
  if (pb == 0 && tid == 0) g_bar = 0u;  // reset grid barrier for fused_sort
  __shared__ float sh[4][512];
  __shared__ float sums[4][48];
  const int p0 = pb * 4;

#pragma unroll
  for (int m = 0; m < 4; ++m) {
    int idx = tid + m * 256;
    int px = idx >> 8, off = idx & 255;
    ((float2*)sh[px])[off] =
        ((const float2*)(g_h1T + (size_t)(p0 + px) * 512))[off];
  }
  __syncthreads();

  const int wid = tid >> 5, lane = tid & 31;
  for (int o = wid; o < 45; o += 8) {
    const float* wrow;
    float bb;
    if (o < 36) { wrow = loc_w + (size_t)o * 512; bb = loc_b[o]; }
    else { int a = o - 36; wrow = score_w + (size_t)(2 * a + 1) * 512; bb = score_b[2 * a + 1]; }
    float s0 = 0.f, s1 = 0.f, s2 = 0.f, s3 = 0.f;
#pragma unroll 4
    for (int c = lane; c < 512; c += 32) {
      float wv = wrow[c];
      s0 = fmaf(wv, sh[0][c], s0);
      s1 = fmaf(wv, sh[1][c], s1);
      s2 = fmaf(wv, sh[2][c], s2);
      s3 = fmaf(wv, sh[3][c], s3);
    }
#pragma unroll
    for (int off = 16; off; off >>= 1) {
      s0 += __shfl_down_sync(0xffffffffu, s0, off);
      s1 += __shfl_down_sync(0xffffffffu, s1, off);
      s2 += __shfl_down_sync(0xffffffffu, s2, off);
      s3 += __shfl_down_sync(0xffffffffu, s3, off);
    }
    if (lane == 0) {
      sums[0][o] = s0 + bb; sums[1][o] = s1 + bb;
      sums[2][o] = s2 + bb; sums[3][o] = s3 + bb;
    }
  }
  __syncthreads();

  if (tid < 36) {
    const int px = tid / 9, a = tid % 9;
    const int p = p0 + px;
    float dy = sums[px][a * 4 + 0], dx = sums[px][a * 4 + 1];
    float dh = sums[px][a * 4 + 2], dw = sums[px][a * 4 + 3];
    float fg = sums[px][36 + a];
    int h = p / IW, w = p % IW;
    float sy = (float)h * 16.f, sx = (float)w * 16.f;
    float ay0 = __fadd_rn(sy, c_ab[a][0]);
    float ax0 = __fadd_rn(sx, c_ab[a][1]);
    float ay1 = __fadd_rn(sy, c_ab[a][2]);
    float ax1 = __fadd_rn(sx, c_ab[a][3]);
    float ah = __fadd_rn(ay1, -ay0);
    float aw = __fadd_rn(ax1, -ax0);
    float acy = __fadd_rn(ay0, __fmul_rn(0.5f, ah));
    float acx = __fadd_rn(ax0, __fmul_rn(0.5f, aw));
    float cy = __fadd_rn(__fmul_rn(dy, ah), acy);
    float cx = __fadd_rn(__fmul_rn(dx, aw), acx);
    float bh = __fmul_rn(expf(dh), ah);
    float bw = __fmul_rn(expf(dw), aw);
    float y1 = fminf(fmaxf(__fadd_rn(cy, -__fmul_rn(0.5f, bh)), 0.f), 608.f);
    float x1 = fminf(fmaxf(__fadd_rn(cx, -__fmul_rn(0.5f, bw)), 0.f), 800.f);
    float y2 = fminf(fmaxf(__fadd_rn(cy,  __fmul_rn(0.5f, bh)), 0.f), 608.f);
    float x2 = fminf(fmaxf(__fadd_rn(cx,  __fmul_rn(0.5f, bw)), 0.f), 800.f);
    bool valid = (__fadd_rn(y2, -y1) >= 16.f) && (__fadd_rn(x2, -x1) >= 16.f);
    float sc = valid ? fg : -__int_as_float(0x7f800000);

    int i = p * 9 + a;
    g_box[i * 4 + 0] = y1; g_box[i * 4 + 1] = x1;
    g_box[i * 4 + 2] = y2; g_box[i * 4 + 3] = x2;
    g_keys[i] = ((ull)f2key(sc) << 32) | (ull)(~(unsigned)i);
  }
}

// ---------------- fused bitonic sort (8 persistent blocks) --------------
__device__ __forceinline__ void grid_sync(unsigned& target) {
  __syncthreads();
  target += 8;
  if (threadIdx.x == 0) {
    __threadfence();
    atomicAdd(&g_bar, 1u);
    while (atomicAdd(&g_bar, 0u) < target) {}
    __threadfence();
  }
  __syncthreads();
}

__global__ __launch_bounds__(1024) void fused_sort() {
  __shared__ ull s[4096];
  const int base = blockIdx.x * 4096;
  const int t = threadIdx.x;
  unsigned bar_t = 0;

#pragma unroll
  for (int m = 0; m < 4; ++m) {
    int l = t + m * 1024, e = base + l;
    s[l] = (e < NANCH) ? g_keys[e] : 0ull;
  }
  __syncthreads();

  for (int k = 2; k <= 4096; k <<= 1) {
    for (int j = k >> 1; j > 0; j >>= 1) {
#pragma unroll
      for (int m = 0; m < 2; ++m) {
        int tt = t + m * 1024;
        int i = ((tt & ~(j - 1)) << 1) | (tt & (j - 1));
        int ix = i | j;
        bool desc = (((base + i) & k) == 0);
        ull a = s[i], b = s[ix];
        if (desc ? (a < b) : (a > b)) { s[i] = b; s[ix] = a; }
      }
      __syncthreads();
    }
  }

#define STORE_TO(buf) do {                                   \
    _Pragma("unroll")                                        \
    for (int m = 0; m < 4; ++m)                              \
      (buf)[base + t + m * 1024] = s[t + m * 1024];          \
  } while (0)

#define COMBINE(buf, K, J) do {                              \
    bool lower = ((base & (J)) == 0);                        \
    bool descC = ((base & (K)) == 0);                        \
    bool takeMax = (lower == descC);                         \
    _Pragma("unroll")                                        \
    for (int m = 0; m < 4; ++m) {                            \
      int l = t + m * 1024;                                  \
      ull v = __ldcg(&(buf)[(base + l) ^ (J)]);              \
      ull mv = s[l];                                         \
      s[l] = takeMax ? (mv > v ? mv : v) : (mv < v ? mv : v);\
    }                                                        \
    __syncthreads();                                         \
  } while (0)

#define TAIL(K) do {                                         \
    bool descT = ((base & (K)) == 0);                        \
    for (int j = 2048; j > 0; j >>= 1) {                     \
      _Pragma("unroll")                                      \
      for (int m = 0; m < 2; ++m) {                          \
        int tt = t + m * 1024;                               \
        int i = ((tt & ~(j - 1)) << 1) | (tt & (j - 1));     \
        int ix = i | j;                                      \
        ull a = s[i], b = s[ix];                             \
        if (descT ? (a < b) : (a > b)) { s[i] = b; s[ix] = a; } \
      }                                                      \
      __syncthreads();                                       \
    }                                                        \
  } while (0)

  STORE_TO(g_keys);  grid_sync(bar_t);
  COMBINE(g_keys, 8192, 4096);  TAIL(8192);

  STORE_TO(g_keys2); grid_sync(bar_t);
  COMBINE(g_keys2, 16384, 8192);

  STORE_TO(g_keys);  grid_sync(bar_t);
  COMBINE(g_keys, 16384, 4096);  TAIL(16384);

  STORE_TO(g_keys2); grid_sync(bar_t);
  COMBINE(g_keys2, 32768, 16384);

  STORE_TO(g_keys);  grid_sync(bar_t);
  COMBINE(g_keys, 32768, 8192);

  STORE_TO(g_keys2); grid_sync(bar_t);
  COMBINE(g_keys2, 32768, 4096);  TAIL(32768);

  if (base < 6144) {
#pragma unroll
    for (int m = 0; m < 4; ++m) {
      int l = t + m * 1024, e = base + l;
      if (e < 6144) {
        ull key = s[l];
        bool valid = (e < PRE_N) && ((unsigned)(key >> 32) > 0x007FFFFFu);
        unsigned bal = __ballot_sync(0xffffffffu, valid);
        if ((t & 31) == 0) ((unsigned*)g_validw)[e >> 5] = bal;
        if (e < PRE_N) {
          unsigned idx = ~(unsigned)(key & 0xffffffffull);
          float4 b = make_float4(0.f, 0.f, 0.f, 0.f);
          if (idx < NANCH) b = ((const float4*)g_box)[idx];
          ((float4*)g_tb)[e] = b;
        }
      }
    }
  }
#undef STORE_TO
#undef COMBINE
#undef TAIL
}

// ------- NMS mask: 128-row x 64-col tiles, fully unrolled inner ---------
__global__ __launch_bounds__(128) void nms_mask() {
  const int cb = blockIdx.x;      // 0..93
  const int rb = blockIdx.y;      // 0..46
  if (cb < 2 * rb) return;
  const int tid = threadIdx.x;
  __shared__ float4 colb[64];
  __shared__ float cola[64];
  const int j0 = cb * 64;
  if (tid < 64) {
    int jj = j0 + tid;
    float4 b = (jj < PRE_N) ? ((const float4*)g_tb)[jj]
                            : make_float4(0.f, 0.f, 0.f, 0.f);
    colb[tid] = b;
    cola[tid] = __fmul_rn(__fadd_rn(b.z, -b.x), __fadd_rn(b.w, -b.y));
  }
  __syncthreads();
  const int i = rb * 128 + tid;
  if (i >= PRE_N) return;
  if (i >= j0 + 64) return;
  float4 r = ((const float4*)g_tb)[i];
  float ra = __fmul_rn(__fadd_rn(r.z, -r.x), __fadd_rn(r.w, -r.y));
  ull bits = 0ull;
#pragma unroll
  for (int q = 0; q < 64; ++q) {
    float4 c = colb[q];
    float ty1 = fmaxf(r.x, c.x);
    float tx1 = fmaxf(r.y, c.y);
    float ty2 = fminf(r.z, c.z);
    float tx2 = fminf(r.w, c.w);
    float ihh = fmaxf(__fadd_rn(ty2, -ty1), 0.f);
    float iww = fmaxf(__fadd_rn(tx2, -tx1), 0.f);
    float inter = __fmul_rn(ihh, iww);
    float uni = fmaxf(__fadd_rn(__fadd_rn(ra, cola[q]), -inter), 1e-9f);
    float d = __fmaf_rn(-0.7f, uni, inter);
    bool sup;
    if (fabsf(d) < 3e-5f * uni)
      sup = (__fdiv_rn(inter, uni) > 0.7f);
    else
      sup = d > 0.f;
    if (sup) bits |= (1ull << q);
  }
  if (j0 <= i) {
    int dq = i - j0;
    bits = (dq >= 63) ? 0ull : (bits & (~0ull << (dq + 1)));
  }
  g_mask[(size_t)i * MASKW + cb] = bits;
}

// ---- NMS scan: ffs bit-walk + parallel row fold, early stop @300 -------
__global__ __launch_bounds__(256) void nms_scan(float* __restrict__ out) {
  __shared__ ull remv[MASKW];
  __shared__ int keptIdx[POST_N];
  __shared__ int wordKept[64];
  __shared__ int s_nk, s_nwk;
  const int tid = threadIdx.x;
  if (tid < MASKW) remv[tid] = 0ull;
  if (tid == 0) s_nk = 0;
  for (int i = tid; i < POST_N * 4; i += 256) out[i] = 0.f;
  __syncthreads();

  for (int w = 0; w < MASKW; ++w) {
    if (tid < 32) {
      ull vw = g_validw[w];
      ull alive = vw & ~remv[w];
      int base = w * 64;
      ull mA = ((alive >> tid) & 1ull) ? g_mask[(size_t)(base + tid) * MASKW + w] : 0ull;
      ull mB = ((alive >> (tid + 32)) & 1ull) ? g_mask[(size_t)(base + tid + 32) * MASKW + w] : 0ull;
      int nk = s_nk, nwk = 0;
      while (alive && nk < POST_N) {
        int q = __ffsll((long long)alive) - 1;
        ull mq = (q < 32) ? __shfl_sync(0xffffffffu, mA, q)
                          : __shfl_sync(0xffffffffu, mB, q - 32);
        if (tid == 0) { keptIdx[nk] = base + q; wordKept[nwk] = base + q; }
        ++nk; ++nwk;
        alive &= ~((1ull << q) | mq);
      }
      if (tid == 0) { s_nk = nk; s_nwk = nwk; }
    }
    __syncthreads();
    int total = s_nwk * MASKW;
    for (int e = tid; e < total; e += 256) {
      int r = e / MASKW, wd = e - r * MASKW;
      ull m = g_mask[(size_t)wordKept[r] * MASKW + wd];
      if (m) atomicOr(&remv[wd], m);
    }
    __syncthreads();
    if (s_nk >= POST_N) break;
  }

  __syncthreads();
  for (int r = tid; r < s_nk; r += 256)
    ((float4*)out)[r] = ((const float4*)g_tb)[keptIdx[r]];
}

// ---------------- launcher ----------------
extern "C" void kernel_launch(void* const* d_in, const int* in_sizes, int n_in,
                              void* d_out, int out_size) {
  const float* x        = (const float*)d_in[0];
  const float* conv1_w  = (const float*)d_in[1];
  const float* conv1_b  = (const float*)d_in[2];
  const float* loc_w    = (const float*)d_in[3];
  const float* loc_b    = (const float*)d_in[4];
  const float* score_w  = (const float*)d_in[5];
  const float* score_b  = (const float*)d_in[6];
  float* out = (float*)d_out;

  dim3 cgrid(7, 5, 8);
  conv3x3_relu<<<cgrid, 256>>>(x, conv1_w, conv1_b);
  rpn_head<<<475, 256>>>(loc_w, loc_b, score_w, score_b);
  fused_sort<<<8, 1024>>>();
  nms_mask<<<dim3(94, 47), 128>>>();
  nms_scan<<<1, 256>>>(out);
}